// round 6
// baseline (speedup 1.0000x reference)
#include <cuda_runtime.h>
#include <stdint.h>
#include <math.h>

// ---------------- problem constants ----------------
static constexpr int B_ = 128, N_ = 200, D_ = 128, H_ = 8, DH_ = 16, L_ = 3, F_ = 2048;
static constexpr int ROWS = B_ * N_;            // 25600
static constexpr int STEPS = 2 * (N_ - 1) + 1;  // 399
static constexpr float SQRTD = 11.313708498984761f;

// ---------------- scratch ----------------
__device__ float g_h[ROWS * D_];
__device__ float g_qkv[ROWS * 3 * D_];
__device__ float g_att[ROWS * D_];
__device__ float g_ffn[ROWS * F_];
__device__ float g_kmat[ROWS * D_];
__device__ float g_hM[ROWS * D_];
__device__ float g_S1[B_ * N_ * N_];
__device__ float g_dr[ROWS];
__device__ float g_gctx[B_ * D_];
__device__ float g_M[D_ * 3 * D_];
__device__ float g_vconst[D_];
__device__ float g_vu[D_];
__device__ float g_qctx[B_ * D_];
__device__ float g_C[ROWS];
__device__ float g_U[ROWS];
__device__ uint2 g_keys[STEPS];
__device__ float g_gum[(size_t)STEPS * ROWS];

// ---------------- f32x2 helpers ----------------
__device__ __forceinline__ void ffma2(unsigned long long& d, unsigned long long a,
                                      unsigned long long b) {
    asm("fma.rn.f32x2 %0, %1, %2, %0;" : "+l"(d) : "l"(a), "l"(b));
}
__device__ __forceinline__ unsigned long long pack2(float lo, float hi) {
    unsigned long long r;
    asm("mov.b64 %0, {%1, %2};" : "=l"(r) : "f"(lo), "f"(hi));
    return r;
}
__device__ __forceinline__ float2 unpack2(unsigned long long v) {
    float2 r;
    asm("mov.b64 {%0, %1}, %2;" : "=f"(r.x), "=f"(r.y) : "l"(v));
    return r;
}

// ---------------- threefry2x32 (exact JAX) ----------------
__device__ __forceinline__ uint32_t rotl32(uint32_t x, int d) {
    return (x << d) | (x >> (32 - d));
}
__device__ __forceinline__ uint2 threefry2x32(uint32_t k0, uint32_t k1,
                                              uint32_t x0, uint32_t x1) {
    uint32_t ks2 = k0 ^ k1 ^ 0x1BD11BDAu;
    x0 += k0; x1 += k1;
    const int r0[4] = {13, 15, 26, 6};
    const int r1[4] = {17, 29, 16, 24};
#pragma unroll
    for (int i = 0; i < 4; i++) { x0 += x1; x1 = rotl32(x1, r0[i]); x1 ^= x0; }
    x0 += k1; x1 += ks2 + 1u;
#pragma unroll
    for (int i = 0; i < 4; i++) { x0 += x1; x1 = rotl32(x1, r1[i]); x1 ^= x0; }
    x0 += ks2; x1 += k0 + 2u;
#pragma unroll
    for (int i = 0; i < 4; i++) { x0 += x1; x1 = rotl32(x1, r0[i]); x1 ^= x0; }
    x0 += k0; x1 += k1 + 3u;
#pragma unroll
    for (int i = 0; i < 4; i++) { x0 += x1; x1 = rotl32(x1, r1[i]); x1 ^= x0; }
    x0 += k1; x1 += ks2 + 4u;
#pragma unroll
    for (int i = 0; i < 4; i++) { x0 += x1; x1 = rotl32(x1, r0[i]); x1 ^= x0; }
    x0 += ks2; x1 += k0 + 5u;
    return make_uint2(x0, x1);
}

__global__ void make_keys_kernel() {
    uint32_t k0 = 0u, k1 = 42u;
    for (int t = 0; t < STEPS; t++) {
        uint2 nk = threefry2x32(k0, k1, 0u, 0u);
        uint2 sk = threefry2x32(k0, k1, 0u, 1u);
        g_keys[t] = sk;
        k0 = nk.x; k1 = nk.y;
    }
}

__global__ void gumbel_kernel() {
    int step = blockIdx.y;
    int i = blockIdx.x * 256 + threadIdx.x;
    if (i >= ROWS) return;
    uint2 key = g_keys[step];
    uint2 y = threefry2x32(key.x, key.y, 0u, (uint32_t)i);
    uint32_t bits = y.x ^ y.y;
    float f = __uint_as_float((bits >> 9) | 0x3f800000u) - 1.0f;
    float u = (f == 0.f) ? 1.17549435e-38f : f;
    g_gum[(size_t)step * ROWS + i] = -logf(-logf(u));
}

// ---------------- embed ----------------
__global__ void embed_kernel(const float* __restrict__ coords,
                             const float* __restrict__ demands,
                             const float* __restrict__ cap,
                             const float* __restrict__ W,
                             const float* __restrict__ bias) {
    int row = blockIdx.x;
    int d = threadIdx.x;
    int b = row / N_;
    float cx = coords[row * 2 + 0];
    float cy = coords[row * 2 + 1];
    float r = demands[row] / cap[b];
    if (d == 0) g_dr[row] = r;
    float v = W[d * 3 + 0] * cx + W[d * 3 + 1] * cy + W[d * 3 + 2] * r + bias[d];
    g_h[(size_t)row * D_ + d] = v;
}

// ---------------- SGEMM 64x128 tile, occ-3: C = A @ W^T (+bias)(+relu) ----------------
__global__ void __launch_bounds__(256, 3)
gemm64(const float* __restrict__ A, const float* __restrict__ W,
       const float* __restrict__ bias, float* __restrict__ C,
       int Nout, int K, int ldw, int relu) {
    __shared__ float As[2][8][64];
    __shared__ float Bs[2][8][128];
    const int tid = threadIdx.x;
    const int tx = tid & 15, ty = tid >> 4;
    const int m0 = blockIdx.y * 64, n0 = blockIdx.x * 128;
    unsigned long long acc2[4][4];
#pragma unroll
    for (int i = 0; i < 4; i++)
#pragma unroll
        for (int j = 0; j < 4; j++) acc2[i][j] = 0ull;

    const int arow = tid >> 1, ahalf = tid & 1;
    const bool aload = tid < 128;
    const float* Aptr = A + (size_t)(m0 + (aload ? arow : 0)) * K + ahalf * 4;
    const float* Wptr = W + (size_t)(n0 + arow) * ldw + ahalf * 4;

    const int KC = K >> 3;
    float4 ra = make_float4(0.f, 0.f, 0.f, 0.f), rb;
    if (aload) ra = *(const float4*)(Aptr);
    rb = *(const float4*)(Wptr);
    if (aload) {
        As[0][ahalf * 4 + 0][arow] = ra.x; As[0][ahalf * 4 + 1][arow] = ra.y;
        As[0][ahalf * 4 + 2][arow] = ra.z; As[0][ahalf * 4 + 3][arow] = ra.w;
    }
    Bs[0][ahalf * 4 + 0][arow] = rb.x; Bs[0][ahalf * 4 + 1][arow] = rb.y;
    Bs[0][ahalf * 4 + 2][arow] = rb.z; Bs[0][ahalf * 4 + 3][arow] = rb.w;
    __syncthreads();

    int buf = 0;
    for (int kc = 0; kc < KC; kc++) {
        if (kc + 1 < KC) {
            if (aload) ra = *(const float4*)(Aptr + (kc + 1) * 8);
            rb = *(const float4*)(Wptr + (kc + 1) * 8);
        }
#pragma unroll
        for (int k = 0; k < 8; k++) {
            ulonglong2 q0 = *(const ulonglong2*)&Bs[buf][k][tx * 4];
            ulonglong2 q1 = *(const ulonglong2*)&Bs[buf][k][64 + tx * 4];
            unsigned long long bp[4] = {q0.x, q0.y, q1.x, q1.y};
            float4 a0 = *(const float4*)&As[buf][k][ty * 4];
            float aa[4] = {a0.x, a0.y, a0.z, a0.w};
#pragma unroll
            for (int i = 0; i < 4; i++) {
                unsigned long long ad = pack2(aa[i], aa[i]);
#pragma unroll
                for (int j = 0; j < 4; j++) ffma2(acc2[i][j], ad, bp[j]);
            }
        }
        if (kc + 1 < KC) {
            int nb = buf ^ 1;
            if (aload) {
                As[nb][ahalf * 4 + 0][arow] = ra.x; As[nb][ahalf * 4 + 1][arow] = ra.y;
                As[nb][ahalf * 4 + 2][arow] = ra.z; As[nb][ahalf * 4 + 3][arow] = ra.w;
            }
            Bs[nb][ahalf * 4 + 0][arow] = rb.x; Bs[nb][ahalf * 4 + 1][arow] = rb.y;
            Bs[nb][ahalf * 4 + 2][arow] = rb.z; Bs[nb][ahalf * 4 + 3][arow] = rb.w;
            __syncthreads();
            buf = nb;
        }
    }

    float bv[8];
#pragma unroll
    for (int j = 0; j < 4; j++) {
        bv[j]     = bias ? bias[n0 + tx * 4 + j]      : 0.f;
        bv[4 + j] = bias ? bias[n0 + 64 + tx * 4 + j] : 0.f;
    }
#pragma unroll
    for (int i = 0; i < 4; i++) {
        int m = m0 + ty * 4 + i;
        float2 p0 = unpack2(acc2[i][0]), p1 = unpack2(acc2[i][1]);
        float2 p2 = unpack2(acc2[i][2]), p3 = unpack2(acc2[i][3]);
        float4 o0, o1;
        o0.x = p0.x + bv[0]; o0.y = p0.y + bv[1]; o0.z = p1.x + bv[2]; o0.w = p1.y + bv[3];
        o1.x = p2.x + bv[4]; o1.y = p2.y + bv[5]; o1.z = p3.x + bv[6]; o1.w = p3.y + bv[7];
        if (relu) {
            o0.x = fmaxf(o0.x, 0.f); o0.y = fmaxf(o0.y, 0.f);
            o0.z = fmaxf(o0.z, 0.f); o0.w = fmaxf(o0.w, 0.f);
            o1.x = fmaxf(o1.x, 0.f); o1.y = fmaxf(o1.y, 0.f);
            o1.z = fmaxf(o1.z, 0.f); o1.w = fmaxf(o1.w, 0.f);
        }
        *(float4*)&C[(size_t)m * Nout + n0 + tx * 4] = o0;
        *(float4*)&C[(size_t)m * Nout + n0 + 64 + tx * 4] = o1;
    }
}

// ---------------- GEMM + residual + LayerNorm fused: h = LN(h + A@W^T + bias) ----------------
__global__ void __launch_bounds__(256, 3)
gemm_ln(const float* __restrict__ A, const float* __restrict__ W,
        const float* __restrict__ bias, float* __restrict__ hio,
        const float* __restrict__ gamma, const float* __restrict__ beta, int K) {
    __shared__ float As[2][8][64];
    __shared__ float Bs[2][8][128];
    const int tid = threadIdx.x;
    const int tx = tid & 15, ty = tid >> 4;
    const int m0 = blockIdx.y * 64;
    unsigned long long acc2[4][4];
#pragma unroll
    for (int i = 0; i < 4; i++)
#pragma unroll
        for (int j = 0; j < 4; j++) acc2[i][j] = 0ull;

    const int arow = tid >> 1, ahalf = tid & 1;
    const bool aload = tid < 128;
    const float* Aptr = A + (size_t)(m0 + (aload ? arow : 0)) * K + ahalf * 4;
    const float* Wptr = W + (size_t)arow * K + ahalf * 4;

    const int KC = K >> 3;
    float4 ra = make_float4(0.f, 0.f, 0.f, 0.f), rb;
    if (aload) ra = *(const float4*)(Aptr);
    rb = *(const float4*)(Wptr);
    if (aload) {
        As[0][ahalf * 4 + 0][arow] = ra.x; As[0][ahalf * 4 + 1][arow] = ra.y;
        As[0][ahalf * 4 + 2][arow] = ra.z; As[0][ahalf * 4 + 3][arow] = ra.w;
    }
    Bs[0][ahalf * 4 + 0][arow] = rb.x; Bs[0][ahalf * 4 + 1][arow] = rb.y;
    Bs[0][ahalf * 4 + 2][arow] = rb.z; Bs[0][ahalf * 4 + 3][arow] = rb.w;
    __syncthreads();

    int buf = 0;
    for (int kc = 0; kc < KC; kc++) {
        if (kc + 1 < KC) {
            if (aload) ra = *(const float4*)(Aptr + (kc + 1) * 8);
            rb = *(const float4*)(Wptr + (kc + 1) * 8);
        }
#pragma unroll
        for (int k = 0; k < 8; k++) {
            ulonglong2 q0 = *(const ulonglong2*)&Bs[buf][k][tx * 4];
            ulonglong2 q1 = *(const ulonglong2*)&Bs[buf][k][64 + tx * 4];
            unsigned long long bp[4] = {q0.x, q0.y, q1.x, q1.y};
            float4 a0 = *(const float4*)&As[buf][k][ty * 4];
            float aa[4] = {a0.x, a0.y, a0.z, a0.w};
#pragma unroll
            for (int i = 0; i < 4; i++) {
                unsigned long long ad = pack2(aa[i], aa[i]);
#pragma unroll
                for (int j = 0; j < 4; j++) ffma2(acc2[i][j], ad, bp[j]);
            }
        }
        if (kc + 1 < KC) {
            int nb = buf ^ 1;
            if (aload) {
                As[nb][ahalf * 4 + 0][arow] = ra.x; As[nb][ahalf * 4 + 1][arow] = ra.y;
                As[nb][ahalf * 4 + 2][arow] = ra.z; As[nb][ahalf * 4 + 3][arow] = ra.w;
            }
            Bs[nb][ahalf * 4 + 0][arow] = rb.x; Bs[nb][ahalf * 4 + 1][arow] = rb.y;
            Bs[nb][ahalf * 4 + 2][arow] = rb.z; Bs[nb][ahalf * 4 + 3][arow] = rb.w;
            __syncthreads();
            buf = nb;
        }
    }

#pragma unroll
    for (int i = 0; i < 4; i++) {
        int m = m0 + ty * 4 + i;
        float2 p0 = unpack2(acc2[i][0]), p1 = unpack2(acc2[i][1]);
        float2 p2 = unpack2(acc2[i][2]), p3 = unpack2(acc2[i][3]);
        float4 h0 = *(const float4*)&hio[(size_t)m * 128 + tx * 4];
        float4 h1 = *(const float4*)&hio[(size_t)m * 128 + 64 + tx * 4];
        float x[8];
        x[0] = p0.x + bias[tx * 4 + 0] + h0.x;
        x[1] = p0.y + bias[tx * 4 + 1] + h0.y;
        x[2] = p1.x + bias[tx * 4 + 2] + h0.z;
        x[3] = p1.y + bias[tx * 4 + 3] + h0.w;
        x[4] = p2.x + bias[64 + tx * 4 + 0] + h1.x;
        x[5] = p2.y + bias[64 + tx * 4 + 1] + h1.y;
        x[6] = p3.x + bias[64 + tx * 4 + 2] + h1.z;
        x[7] = p3.y + bias[64 + tx * 4 + 3] + h1.w;
        float s = 0.f;
#pragma unroll
        for (int j = 0; j < 8; j++) s += x[j];
#pragma unroll
        for (int off = 1; off < 16; off <<= 1)
            s += __shfl_xor_sync(0xffffffffu, s, off);
        float mean = s * 0.0078125f;
        float c[8], v = 0.f;
#pragma unroll
        for (int j = 0; j < 8; j++) { c[j] = x[j] - mean; v += c[j] * c[j]; }
#pragma unroll
        for (int off = 1; off < 16; off <<= 1)
            v += __shfl_xor_sync(0xffffffffu, v, off);
        float den = sqrtf(v * 0.0078125f + 1e-5f);
        float4 o0, o1;
        o0.x = c[0] / den * gamma[tx * 4 + 0] + beta[tx * 4 + 0];
        o0.y = c[1] / den * gamma[tx * 4 + 1] + beta[tx * 4 + 1];
        o0.z = c[2] / den * gamma[tx * 4 + 2] + beta[tx * 4 + 2];
        o0.w = c[3] / den * gamma[tx * 4 + 3] + beta[tx * 4 + 3];
        o1.x = c[4] / den * gamma[64 + tx * 4 + 0] + beta[64 + tx * 4 + 0];
        o1.y = c[5] / den * gamma[64 + tx * 4 + 1] + beta[64 + tx * 4 + 1];
        o1.z = c[6] / den * gamma[64 + tx * 4 + 2] + beta[64 + tx * 4 + 2];
        o1.w = c[7] / den * gamma[64 + tx * 4 + 3] + beta[64 + tx * 4 + 3];
        *(float4*)&hio[(size_t)m * 128 + tx * 4] = o0;
        *(float4*)&hio[(size_t)m * 128 + 64 + tx * 4] = o1;
    }
}

// ---------------- batched bounded GEMM (S1) ----------------
__global__ void __launch_bounds__(256, 3)
gemm_batched(const float* __restrict__ A0, const float* __restrict__ W0,
             float* __restrict__ C0, int M, int Nout, int K,
             long long sA, long long sW, long long sC) {
    __shared__ float As[2][8][64];
    __shared__ float Bs[2][8][128];
    const float* A = A0 + (long long)blockIdx.z * sA;
    const float* W = W0 + (long long)blockIdx.z * sW;
    float* C = C0 + (long long)blockIdx.z * sC;
    const int tid = threadIdx.x;
    const int tx = tid & 15, ty = tid >> 4;
    const int m0 = blockIdx.y * 64, n0 = blockIdx.x * 128;
    unsigned long long acc2[4][4];
#pragma unroll
    for (int i = 0; i < 4; i++)
#pragma unroll
        for (int j = 0; j < 4; j++) acc2[i][j] = 0ull;

    const int arow = tid >> 1, ahalf = tid & 1;
    const bool aload = tid < 128;
    const bool aok = aload && (m0 + arow < M);
    const bool wok = (n0 + arow < Nout);
    const float* Aptr = A + (size_t)(aok ? (m0 + arow) : 0) * K + ahalf * 4;
    const float* Wptr = W + (size_t)(wok ? (n0 + arow) : 0) * K + ahalf * 4;

    const int KC = K >> 3;
    float4 ra = make_float4(0.f, 0.f, 0.f, 0.f), rb;
    if (aload) ra = *(const float4*)(Aptr);
    rb = *(const float4*)(Wptr);
    if (aload) {
        As[0][ahalf * 4 + 0][arow] = ra.x; As[0][ahalf * 4 + 1][arow] = ra.y;
        As[0][ahalf * 4 + 2][arow] = ra.z; As[0][ahalf * 4 + 3][arow] = ra.w;
    }
    Bs[0][ahalf * 4 + 0][arow] = rb.x; Bs[0][ahalf * 4 + 1][arow] = rb.y;
    Bs[0][ahalf * 4 + 2][arow] = rb.z; Bs[0][ahalf * 4 + 3][arow] = rb.w;
    __syncthreads();

    int buf = 0;
    for (int kc = 0; kc < KC; kc++) {
        if (kc + 1 < KC) {
            if (aload) ra = *(const float4*)(Aptr + (kc + 1) * 8);
            rb = *(const float4*)(Wptr + (kc + 1) * 8);
        }
#pragma unroll
        for (int k = 0; k < 8; k++) {
            ulonglong2 q0 = *(const ulonglong2*)&Bs[buf][k][tx * 4];
            ulonglong2 q1 = *(const ulonglong2*)&Bs[buf][k][64 + tx * 4];
            unsigned long long bp[4] = {q0.x, q0.y, q1.x, q1.y};
            float4 a0 = *(const float4*)&As[buf][k][ty * 4];
            float aa[4] = {a0.x, a0.y, a0.z, a0.w};
#pragma unroll
            for (int i = 0; i < 4; i++) {
                unsigned long long ad = pack2(aa[i], aa[i]);
#pragma unroll
                for (int j = 0; j < 4; j++) ffma2(acc2[i][j], ad, bp[j]);
            }
        }
        if (kc + 1 < KC) {
            int nb = buf ^ 1;
            if (aload) {
                As[nb][ahalf * 4 + 0][arow] = ra.x; As[nb][ahalf * 4 + 1][arow] = ra.y;
                As[nb][ahalf * 4 + 2][arow] = ra.z; As[nb][ahalf * 4 + 3][arow] = ra.w;
            }
            Bs[nb][ahalf * 4 + 0][arow] = rb.x; Bs[nb][ahalf * 4 + 1][arow] = rb.y;
            Bs[nb][ahalf * 4 + 2][arow] = rb.z; Bs[nb][ahalf * 4 + 3][arow] = rb.w;
            __syncthreads();
            buf = nb;
        }
    }

#pragma unroll
    for (int i = 0; i < 4; i++) {
        int m = m0 + ty * 4 + i;
        if (m >= M) continue;
        float2 p0 = unpack2(acc2[i][0]), p1 = unpack2(acc2[i][1]);
        float2 p2 = unpack2(acc2[i][2]), p3 = unpack2(acc2[i][3]);
        int c0 = n0 + tx * 4, c1 = n0 + 64 + tx * 4;
        if (c0 + 3 < Nout) {
            float4 o; o.x = p0.x; o.y = p0.y; o.z = p1.x; o.w = p1.y;
            *(float4*)&C[(size_t)m * Nout + c0] = o;
        }
        if (c1 + 3 < Nout) {
            float4 o; o.x = p2.x; o.y = p2.y; o.z = p3.x; o.w = p3.y;
            *(float4*)&C[(size_t)m * Nout + c1] = o;
        }
    }
}

// ---------------- attention ----------------
__global__ void __launch_bounds__(256)
attention_smem(const float* __restrict__ qkv, float* __restrict__ out) {
    int bh = blockIdx.x;
    int b = bh >> 3, h = bh & 7;
    __shared__ float QsT[DH_][208], KsT[DH_][208], VsT[DH_][208];
    const float* base = qkv + (size_t)b * N_ * 384 + h * DH_;
    int tid = threadIdx.x;
    for (int i = tid; i < N_ * DH_; i += 256) {
        int n = i >> 4, d = i & 15;
        const float* rp = base + (size_t)n * 384 + d;
        QsT[d][n] = rp[0];
        KsT[d][n] = rp[128];
        VsT[d][n] = rp[256];
    }
    __syncthreads();
    int warp = tid >> 5, lane = tid & 31;
    for (int q = warp; q < N_; q += 8) {
        float qv[DH_];
#pragma unroll
        for (int d = 0; d < DH_; d++) qv[d] = QsT[d][q];
        float s[7];
        float mx = -INFINITY;
#pragma unroll
        for (int j = 0; j < 7; j++) {
            int k = lane + 32 * j;
            float a = 0.f;
            if (k < N_) {
#pragma unroll
                for (int d = 0; d < DH_; d++) a += qv[d] * KsT[d][k];
                a *= 0.25f;
            } else a = -INFINITY;
            s[j] = a;
            mx = fmaxf(mx, a);
        }
#pragma unroll
        for (int off = 16; off; off >>= 1)
            mx = fmaxf(mx, __shfl_xor_sync(0xffffffffu, mx, off));
        float p[7];
        float sum = 0.f;
#pragma unroll
        for (int j = 0; j < 7; j++) {
            int k = lane + 32 * j;
            p[j] = (k < N_) ? expf(s[j] - mx) : 0.f;
            sum += p[j];
        }
#pragma unroll
        for (int off = 16; off; off >>= 1)
            sum += __shfl_xor_sync(0xffffffffu, sum, off);
        float inv = 1.f / sum;
        float o[DH_];
#pragma unroll
        for (int d = 0; d < DH_; d++) o[d] = 0.f;
#pragma unroll
        for (int j = 0; j < 7; j++) {
            int k = lane + 32 * j;
            if (k < N_) {
                float wgt = p[j] * inv;
#pragma unroll
                for (int d = 0; d < DH_; d++) o[d] += wgt * VsT[d][k];
            }
        }
#pragma unroll
        for (int d = 0; d < DH_; d++) {
            float v = o[d];
#pragma unroll
            for (int off = 16; off; off >>= 1)
                v += __shfl_xor_sync(0xffffffffu, v, off);
            if (lane == d)
                out[((size_t)b * N_ + q) * D_ + h * DH_ + d] = v;
        }
    }
}

// ---------------- small precompute kernels ----------------
__global__ void compute_M_kernel(const float* __restrict__ Wq, const float* __restrict__ Wctx) {
    int d = blockIdx.y;
    int c = blockIdx.x * blockDim.x + threadIdx.x;
    if (c >= 3 * D_) return;
    float acc = 0.f;
    for (int k = 0; k < D_; k++) acc += Wq[d * D_ + k] * Wctx[k * (3 * D_) + c];
    g_M[d * (3 * D_) + c] = acc;
}

__global__ void compute_vecs_kernel(const float* __restrict__ Wq, const float* __restrict__ bctx,
                                    const float* __restrict__ Wcap, const float* __restrict__ bcap) {
    int d = threadIdx.x;
    float a = 0.f, u = 0.f, bq = 0.f;
    for (int k = 0; k < D_; k++) {
        float m = g_M[d * (3 * D_) + 2 * D_ + k];
        a += m * bcap[k];
        u += m * Wcap[k];
        bq += Wq[d * D_ + k] * bctx[k];
    }
    g_vconst[d] = a + bq;
    g_vu[d] = u;
}

__global__ void compute_gctx_kernel() {
    int b = blockIdx.x, d = threadIdx.x;
    float s = 0.f;
    for (int n = 0; n < N_; n++) s += g_h[((size_t)b * N_ + n) * D_ + d];
    g_gctx[b * D_ + d] = s / (float)N_;
}

__global__ void compute_qctx_kernel() {
    int b = blockIdx.x, d = threadIdx.x;
    float a = g_vconst[d];
    for (int k = 0; k < D_; k++) a += g_M[d * (3 * D_) + D_ + k] * g_gctx[b * D_ + k];
    g_qctx[b * D_ + d] = a;
}

__global__ void compute_CU_kernel() {
    int i = blockIdx.x * blockDim.x + threadIdx.x;
    if (i >= ROWS) return;
    int b = i / N_;
    const float* kr = g_kmat + (size_t)i * D_;
    float c = 0.f, u = 0.f;
    for (int d = 0; d < D_; d++) {
        c += kr[d] * g_qctx[b * D_ + d];
        u += kr[d] * g_vu[d];
    }
    g_C[i] = c;
    g_U[i] = u;
}

// ---------------- decode: one warp per batch, no block syncs ----------------
__device__ __forceinline__ float pick7(const float a[7], int s) {
    float r = a[0];
    if (s == 1) r = a[1];
    if (s == 2) r = a[2];
    if (s == 3) r = a[3];
    if (s == 4) r = a[4];
    if (s == 5) r = a[5];
    if (s == 6) r = a[6];
    return r;
}

__global__ void __launch_bounds__(32)
decode_warp(float* __restrict__ path_out, float* __restrict__ lp_out) {
    const unsigned FULL = 0xffffffffu;
    int b = blockIdx.x;
    int lane = threadIdx.x;
    float drv[7], Cv[7], Uv[7], s1[7], gum[7];
    unsigned vism = 0;  // bit j: node lane+32j visited
#pragma unroll
    for (int j = 0; j < 7; j++) {
        int n = lane + 32 * j;
        if (n < N_) {
            drv[j] = g_dr[b * N_ + n];
            Cv[j] = g_C[b * N_ + n];
            Uv[j] = g_U[b * N_ + n];
            s1[j] = g_S1[(size_t)(b * N_) * N_ + n];
            gum[j] = g_gum[(size_t)b * N_ + n];
        } else { drv[j] = 0.f; Cv[j] = 0.f; Uv[j] = 0.f; s1[j] = 0.f; gum[j] = 0.f; }
    }
    float rem = 1.0f, acc = 0.f;
    int cur = 0, cnt = N_ - 1;
    bool done = false;
    if (lane == 0) path_out[(size_t)b * (STEPS + 1)] = 0.0f;

    for (int step = 0; step < STEPS; step++) {
        bool anyf = false, anyu = false;
#pragma unroll
        for (int j = 0; j < 7; j++) {
            int n = lane + 32 * j;
            bool valid = (n >= 1) && (n < N_);
            bool vis = (vism >> j) & 1u;
            if (valid && !vis) {
                anyu = true;
                if (drv[j] <= rem) anyf = true;
            }
        }
        bool has_feas = __any_sync(FULL, anyf);
        bool all_served = !__any_sync(FULL, anyu);

        bool at_depot = (cur == 0) && !done;
        bool not_depot = (cur != 0) && !done;
        bool depot_mask = (at_depot && has_feas) ||
                          (not_depot && has_feas && !all_served);
        bool force_depot = (all_served && (cur != 0) && !done) ||
                           (not_depot && !has_feas) || done;

        float mloc[7];
        float lmax = -INFINITY, lkey = -INFINITY;
        int lidx = 1000;
#pragma unroll
        for (int j = 0; j < 7; j++) {
            int n = lane + 32 * j;
            if (n < N_) {
                bool vis = (vism >> j) & 1u;
                bool infeas = vis || (drv[j] > rem);
                if (n == 0) infeas = infeas || depot_mask;
                float logit = (s1[j] + Cv[j] + rem * Uv[j]) / SQRTD;
                float m = infeas ? -1e9f : logit;
                mloc[j] = m;
                float k = m + gum[j];
                lmax = fmaxf(lmax, m);
                if (k > lkey) { lkey = k; lidx = n; }  // ascending n -> first-idx
            } else mloc[j] = -INFINITY;
        }
        // warp argmax (min-index tiebreak) + global max
        float kv = lkey, mx = lmax;
        int ki = lidx;
#pragma unroll
        for (int off = 16; off; off >>= 1) {
            mx = fmaxf(mx, __shfl_xor_sync(FULL, mx, off));
            float kv2 = __shfl_xor_sync(FULL, kv, off);
            int ki2 = __shfl_xor_sync(FULL, ki, off);
            if (kv2 > kv || (kv2 == kv && ki2 < ki)) { kv = kv2; ki = ki2; }
        }
        int sel = force_depot ? 0 : ki;
        // prefetch next S1 row + gumbel (overlaps the log-softmax math below)
        float s1n[7], gumn[7];
        if (step + 1 < STEPS) {
#pragma unroll
            for (int j = 0; j < 7; j++) {
                int n = lane + 32 * j;
                if (n < N_) {
                    s1n[j] = g_S1[(size_t)(b * N_ + sel) * N_ + n];
                    gumn[j] = g_gum[(size_t)(step + 1) * ROWS + b * N_ + n];
                } else { s1n[j] = 0.f; gumn[j] = 0.f; }
            }
        }
        // logsumexp
        float e = 0.f;
#pragma unroll
        for (int j = 0; j < 7; j++) {
            int n = lane + 32 * j;
            if (n < N_) e += expf(mloc[j] - mx);
        }
#pragma unroll
        for (int off = 16; off; off >>= 1)
            e += __shfl_xor_sync(FULL, e, off);

        int slot = sel >> 5, owner = sel & 31;
        float msel = __shfl_sync(FULL, pick7(mloc, slot), owner);
        float dsel = __shfl_sync(FULL, pick7(drv, slot), owner);
        unsigned vsel = __shfl_sync(FULL, (vism >> slot) & 1u, owner);
        float slp = force_depot ? 0.f : (msel - mx - logf(e));
        bool isd = (sel == 0);
        float nr = isd ? 1.0f : (rem - dsel);
        rem = fminf(fmaxf(nr, 0.f), 1.f);
        if (!isd && !vsel) {
            cnt--;
            if (lane == owner) vism |= 1u << slot;
        }
        cur = sel;
        done = done || (cnt == 0 && isd);
        acc += slp;
        if (lane == 0) path_out[(size_t)b * (STEPS + 1) + 1 + step] = (float)sel;
#pragma unroll
        for (int j = 0; j < 7; j++) { s1[j] = s1n[j]; gum[j] = gumn[j]; }
    }
    if (lane == 0 && lp_out) lp_out[b] = acc;
}

// ---------------- launch ----------------
extern "C" void kernel_launch(void* const* d_in, const int* in_sizes, int n_in,
                              void* d_out, int out_size) {
    int perm[23];
    for (int i = 0; i < 23; i++) perm[i] = i;
    if (n_in >= 23 && in_sizes[0] == 786432) {
        const int m[23] = {15,16,14,17,18,7,13,5,12,0,8,1,9,20,19,22,21,6,4,2,10,3,11};
        for (int i = 0; i < 23; i++) perm[i] = m[i];
    }
    const float* coords   = (const float*)d_in[perm[0]];
    const float* demands  = (const float*)d_in[perm[1]];
    const float* capacity = (const float*)d_in[perm[2]];
    const float* embed_W  = (const float*)d_in[perm[3]];
    const float* embed_b  = (const float*)d_in[perm[4]];
    const float* Wqkv     = (const float*)d_in[perm[5]];
    const float* bqkv     = (const float*)d_in[perm[6]];
    const float* Wo       = (const float*)d_in[perm[7]];
    const float* bo       = (const float*)d_in[perm[8]];
    const float* W1       = (const float*)d_in[perm[9]];
    const float* b1       = (const float*)d_in[perm[10]];
    const float* W2       = (const float*)d_in[perm[11]];
    const float* b2       = (const float*)d_in[perm[12]];
    const float* ln1_g    = (const float*)d_in[perm[13]];
    const float* ln1_b    = (const float*)d_in[perm[14]];
    const float* ln2_g    = (const float*)d_in[perm[15]];
    const float* ln2_b    = (const float*)d_in[perm[16]];
    const float* Wq       = (const float*)d_in[perm[17]];
    const float* Wk       = (const float*)d_in[perm[18]];
    const float* Wcap     = (const float*)d_in[perm[19]];
    const float* bcap     = (const float*)d_in[perm[20]];
    const float* Wctx     = (const float*)d_in[perm[21]];
    const float* bctx     = (const float*)d_in[perm[22]];

    float *g_h_p, *g_qkv_p, *g_att_p, *g_ffn_p, *g_kmat_p, *g_hM_p, *g_S1_p, *g_M_p;
    cudaGetSymbolAddress((void**)&g_h_p, g_h);
    cudaGetSymbolAddress((void**)&g_qkv_p, g_qkv);
    cudaGetSymbolAddress((void**)&g_att_p, g_att);
    cudaGetSymbolAddress((void**)&g_ffn_p, g_ffn);
    cudaGetSymbolAddress((void**)&g_kmat_p, g_kmat);
    cudaGetSymbolAddress((void**)&g_hM_p, g_hM);
    cudaGetSymbolAddress((void**)&g_S1_p, g_S1);
    cudaGetSymbolAddress((void**)&g_M_p, g_M);

    embed_kernel<<<ROWS, 128>>>(coords, demands, capacity, embed_W, embed_b);
    make_keys_kernel<<<1, 1>>>();
    gumbel_kernel<<<dim3(100, STEPS), 256>>>();

    for (int i = 0; i < L_; i++) {
        // QKV: 25600 x 384, K=128
        gemm64<<<dim3(3, 400), 256>>>(
            g_h_p, Wqkv + (size_t)i * 384 * 128, bqkv + i * 384, g_qkv_p,
            384, 128, 128, 0);
        attention_smem<<<B_ * H_, 256>>>(g_qkv_p, g_att_p);
        // Wo + residual + LN1
        gemm_ln<<<dim3(1, 400), 256>>>(
            g_att_p, Wo + (size_t)i * 128 * 128, bo + i * 128, g_h_p,
            ln1_g + i * 128, ln1_b + i * 128, 128);
        // FFN1: 25600 x 2048, K=128, relu
        gemm64<<<dim3(16, 400), 256>>>(
            g_h_p, W1 + (size_t)i * F_ * 128, b1 + i * F_, g_ffn_p,
            F_, 128, 128, 1);
        // FFN2 + residual + LN2 (K=2048)
        gemm_ln<<<dim3(1, 400), 256>>>(
            g_ffn_p, W2 + (size_t)i * 128 * F_, b2 + i * 128, g_h_p,
            ln2_g + i * 128, ln2_b + i * 128, F_);
    }

    compute_gctx_kernel<<<B_, 128>>>();
    compute_M_kernel<<<dim3(3, 128), 128>>>(Wq, Wctx);
    compute_vecs_kernel<<<1, 128>>>(Wq, bctx, Wcap, bcap);
    compute_qctx_kernel<<<B_, 128>>>();
    gemm64<<<dim3(1, 400), 256>>>(g_h_p, Wk, nullptr, g_kmat_p, 128, 128, 128, 0);
    gemm64<<<dim3(1, 400), 256>>>(g_h_p, g_M_p, nullptr, g_hM_p, 128, 128, 384, 0);
    gemm_batched<<<dim3(2, 4, B_), 256>>>(
        g_hM_p, g_kmat_p, g_S1_p, N_, N_, 128,
        (long long)N_ * 128, (long long)N_ * 128, (long long)N_ * N_);
    compute_CU_kernel<<<(ROWS + 255) / 256, 256>>>();

    float* out_f = (float*)d_out;
    float* lp_out = (out_size >= B_ * (STEPS + 1) + B_) ? (out_f + B_ * (STEPS + 1)) : nullptr;
    decode_warp<<<B_, 32>>>(out_f, lp_out);
}

// round 7
// speedup vs baseline: 1.0834x; 1.0834x over previous
#include <cuda_runtime.h>
#include <stdint.h>
#include <math.h>

// ---------------- problem constants ----------------
static constexpr int B_ = 128, N_ = 200, D_ = 128, H_ = 8, DH_ = 16, L_ = 3, F_ = 2048;
static constexpr int ROWS = B_ * N_;            // 25600
static constexpr int STEPS = 2 * (N_ - 1) + 1;  // 399
static constexpr float SQRTD = 11.313708498984761f;

// ---------------- scratch ----------------
__device__ float g_h[ROWS * D_];
__device__ float g_qkv[ROWS * 3 * D_];
__device__ float g_att[ROWS * D_];
__device__ float g_ffn[ROWS * F_];
__device__ float g_kmat[ROWS * D_];
__device__ float g_hM[ROWS * D_];
__device__ float g_S1[B_ * N_ * N_];
__device__ float g_dr[ROWS];
__device__ float g_gctx[B_ * D_];
__device__ float g_M[D_ * 3 * D_];
__device__ float g_vconst[D_];
__device__ float g_vu[D_];
__device__ float g_qctx[B_ * D_];
__device__ float g_C[ROWS];
__device__ float g_U[ROWS];
__device__ uint2 g_keys[STEPS];
__device__ float g_gum[(size_t)STEPS * ROWS];

// ---------------- f32x2 helpers ----------------
__device__ __forceinline__ void ffma2(unsigned long long& d, unsigned long long a,
                                      unsigned long long b) {
    asm("fma.rn.f32x2 %0, %1, %2, %0;" : "+l"(d) : "l"(a), "l"(b));
}
__device__ __forceinline__ unsigned long long pack2(float lo, float hi) {
    unsigned long long r;
    asm("mov.b64 %0, {%1, %2};" : "=l"(r) : "f"(lo), "f"(hi));
    return r;
}
__device__ __forceinline__ float2 unpack2(unsigned long long v) {
    float2 r;
    asm("mov.b64 {%0, %1}, %2;" : "=f"(r.x), "=f"(r.y) : "l"(v));
    return r;
}

// ---------------- threefry2x32 (exact JAX) ----------------
__device__ __forceinline__ uint32_t rotl32(uint32_t x, int d) {
    return (x << d) | (x >> (32 - d));
}
__device__ __forceinline__ uint2 threefry2x32(uint32_t k0, uint32_t k1,
                                              uint32_t x0, uint32_t x1) {
    uint32_t ks2 = k0 ^ k1 ^ 0x1BD11BDAu;
    x0 += k0; x1 += k1;
    const int r0[4] = {13, 15, 26, 6};
    const int r1[4] = {17, 29, 16, 24};
#pragma unroll
    for (int i = 0; i < 4; i++) { x0 += x1; x1 = rotl32(x1, r0[i]); x1 ^= x0; }
    x0 += k1; x1 += ks2 + 1u;
#pragma unroll
    for (int i = 0; i < 4; i++) { x0 += x1; x1 = rotl32(x1, r1[i]); x1 ^= x0; }
    x0 += ks2; x1 += k0 + 2u;
#pragma unroll
    for (int i = 0; i < 4; i++) { x0 += x1; x1 = rotl32(x1, r0[i]); x1 ^= x0; }
    x0 += k0; x1 += k1 + 3u;
#pragma unroll
    for (int i = 0; i < 4; i++) { x0 += x1; x1 = rotl32(x1, r1[i]); x1 ^= x0; }
    x0 += k1; x1 += ks2 + 4u;
#pragma unroll
    for (int i = 0; i < 4; i++) { x0 += x1; x1 = rotl32(x1, r0[i]); x1 ^= x0; }
    x0 += ks2; x1 += k0 + 5u;
    return make_uint2(x0, x1);
}

__global__ void make_keys_kernel() {
    uint32_t k0 = 0u, k1 = 42u;
    for (int t = 0; t < STEPS; t++) {
        uint2 nk = threefry2x32(k0, k1, 0u, 0u);
        uint2 sk = threefry2x32(k0, k1, 0u, 1u);
        g_keys[t] = sk;
        k0 = nk.x; k1 = nk.y;
    }
}

__global__ void gumbel_kernel() {
    int step = blockIdx.y;
    int i = blockIdx.x * 256 + threadIdx.x;
    if (i >= ROWS) return;
    uint2 key = g_keys[step];
    uint2 y = threefry2x32(key.x, key.y, 0u, (uint32_t)i);
    uint32_t bits = y.x ^ y.y;
    float f = __uint_as_float((bits >> 9) | 0x3f800000u) - 1.0f;
    float u = (f == 0.f) ? 1.17549435e-38f : f;
    g_gum[(size_t)step * ROWS + i] = -logf(-logf(u));
}

// ---------------- embed ----------------
__global__ void embed_kernel(const float* __restrict__ coords,
                             const float* __restrict__ demands,
                             const float* __restrict__ cap,
                             const float* __restrict__ W,
                             const float* __restrict__ bias) {
    int row = blockIdx.x;
    int d = threadIdx.x;
    int b = row / N_;
    float cx = coords[row * 2 + 0];
    float cy = coords[row * 2 + 1];
    float r = demands[row] / cap[b];
    if (d == 0) g_dr[row] = r;
    float v = W[d * 3 + 0] * cx + W[d * 3 + 1] * cy + W[d * 3 + 2] * r + bias[d];
    g_h[(size_t)row * D_ + d] = v;
}

// ---------------- SGEMM 128x128 tile, occ-2 (best AI): C = A @ W^T (+bias)(+relu) ---------
__global__ void __launch_bounds__(256, 2)
gemm128(const float* __restrict__ A, const float* __restrict__ W,
        const float* __restrict__ bias, float* __restrict__ C,
        int Nout, int K, int ldw, int relu) {
    __shared__ float As[2][8][128];
    __shared__ float Bs[2][8][128];
    const int tid = threadIdx.x;
    const int tx = tid & 15, ty = tid >> 4;
    const int m0 = blockIdx.y * 128, n0 = blockIdx.x * 128;
    unsigned long long acc2[8][4];
#pragma unroll
    for (int i = 0; i < 8; i++)
#pragma unroll
        for (int j = 0; j < 4; j++) acc2[i][j] = 0ull;

    const int arow = tid >> 1, ahalf = tid & 1;
    const float* Aptr = A + (size_t)(m0 + arow) * K + ahalf * 4;
    const float* Wptr = W + (size_t)(n0 + arow) * ldw + ahalf * 4;

    const int KC = K >> 3;
    float4 ra = *(const float4*)(Aptr);
    float4 rb = *(const float4*)(Wptr);
    As[0][ahalf * 4 + 0][arow] = ra.x; As[0][ahalf * 4 + 1][arow] = ra.y;
    As[0][ahalf * 4 + 2][arow] = ra.z; As[0][ahalf * 4 + 3][arow] = ra.w;
    Bs[0][ahalf * 4 + 0][arow] = rb.x; Bs[0][ahalf * 4 + 1][arow] = rb.y;
    Bs[0][ahalf * 4 + 2][arow] = rb.z; Bs[0][ahalf * 4 + 3][arow] = rb.w;
    __syncthreads();

    int buf = 0;
    for (int kc = 0; kc < KC; kc++) {
        if (kc + 1 < KC) {
            ra = *(const float4*)(Aptr + (kc + 1) * 8);
            rb = *(const float4*)(Wptr + (kc + 1) * 8);
        }
#pragma unroll
        for (int k = 0; k < 8; k++) {
            ulonglong2 q0 = *(const ulonglong2*)&Bs[buf][k][tx * 4];
            ulonglong2 q1 = *(const ulonglong2*)&Bs[buf][k][64 + tx * 4];
            unsigned long long bp[4] = {q0.x, q0.y, q1.x, q1.y};
            float4 a0 = *(const float4*)&As[buf][k][ty * 4];
            float4 a1 = *(const float4*)&As[buf][k][64 + ty * 4];
            float aa[8] = {a0.x, a0.y, a0.z, a0.w, a1.x, a1.y, a1.z, a1.w};
#pragma unroll
            for (int i = 0; i < 8; i++) {
                unsigned long long ad = pack2(aa[i], aa[i]);
#pragma unroll
                for (int j = 0; j < 4; j++) ffma2(acc2[i][j], ad, bp[j]);
            }
        }
        if (kc + 1 < KC) {
            int nb = buf ^ 1;
            As[nb][ahalf * 4 + 0][arow] = ra.x; As[nb][ahalf * 4 + 1][arow] = ra.y;
            As[nb][ahalf * 4 + 2][arow] = ra.z; As[nb][ahalf * 4 + 3][arow] = ra.w;
            Bs[nb][ahalf * 4 + 0][arow] = rb.x; Bs[nb][ahalf * 4 + 1][arow] = rb.y;
            Bs[nb][ahalf * 4 + 2][arow] = rb.z; Bs[nb][ahalf * 4 + 3][arow] = rb.w;
            __syncthreads();
            buf = nb;
        }
    }

    float bv[8];
#pragma unroll
    for (int j = 0; j < 4; j++) {
        bv[j]     = bias ? bias[n0 + tx * 4 + j]      : 0.f;
        bv[4 + j] = bias ? bias[n0 + 64 + tx * 4 + j] : 0.f;
    }
#pragma unroll
    for (int i = 0; i < 8; i++) {
        int m = m0 + ((i < 4) ? (ty * 4 + i) : (64 + ty * 4 + (i - 4)));
        float2 p0 = unpack2(acc2[i][0]), p1 = unpack2(acc2[i][1]);
        float2 p2 = unpack2(acc2[i][2]), p3 = unpack2(acc2[i][3]);
        float4 o0, o1;
        o0.x = p0.x + bv[0]; o0.y = p0.y + bv[1]; o0.z = p1.x + bv[2]; o0.w = p1.y + bv[3];
        o1.x = p2.x + bv[4]; o1.y = p2.y + bv[5]; o1.z = p3.x + bv[6]; o1.w = p3.y + bv[7];
        if (relu) {
            o0.x = fmaxf(o0.x, 0.f); o0.y = fmaxf(o0.y, 0.f);
            o0.z = fmaxf(o0.z, 0.f); o0.w = fmaxf(o0.w, 0.f);
            o1.x = fmaxf(o1.x, 0.f); o1.y = fmaxf(o1.y, 0.f);
            o1.z = fmaxf(o1.z, 0.f); o1.w = fmaxf(o1.w, 0.f);
        }
        *(float4*)&C[(size_t)m * Nout + n0 + tx * 4] = o0;
        *(float4*)&C[(size_t)m * Nout + n0 + 64 + tx * 4] = o1;
    }
}

// ---------------- GEMM(128x128) + residual + LayerNorm fused: h = LN(h + A@W^T + b) ------
__global__ void __launch_bounds__(256, 2)
gemm_ln128(const float* __restrict__ A, const float* __restrict__ W,
           const float* __restrict__ bias, float* __restrict__ hio,
           const float* __restrict__ gamma, const float* __restrict__ beta, int K) {
    __shared__ float As[2][8][128];
    __shared__ float Bs[2][8][128];
    const int tid = threadIdx.x;
    const int tx = tid & 15, ty = tid >> 4;
    const int m0 = blockIdx.y * 128;
    unsigned long long acc2[8][4];
#pragma unroll
    for (int i = 0; i < 8; i++)
#pragma unroll
        for (int j = 0; j < 4; j++) acc2[i][j] = 0ull;

    const int arow = tid >> 1, ahalf = tid & 1;
    const float* Aptr = A + (size_t)(m0 + arow) * K + ahalf * 4;
    const float* Wptr = W + (size_t)arow * K + ahalf * 4;

    const int KC = K >> 3;
    float4 ra = *(const float4*)(Aptr);
    float4 rb = *(const float4*)(Wptr);
    As[0][ahalf * 4 + 0][arow] = ra.x; As[0][ahalf * 4 + 1][arow] = ra.y;
    As[0][ahalf * 4 + 2][arow] = ra.z; As[0][ahalf * 4 + 3][arow] = ra.w;
    Bs[0][ahalf * 4 + 0][arow] = rb.x; Bs[0][ahalf * 4 + 1][arow] = rb.y;
    Bs[0][ahalf * 4 + 2][arow] = rb.z; Bs[0][ahalf * 4 + 3][arow] = rb.w;
    __syncthreads();

    int buf = 0;
    for (int kc = 0; kc < KC; kc++) {
        if (kc + 1 < KC) {
            ra = *(const float4*)(Aptr + (kc + 1) * 8);
            rb = *(const float4*)(Wptr + (kc + 1) * 8);
        }
#pragma unroll
        for (int k = 0; k < 8; k++) {
            ulonglong2 q0 = *(const ulonglong2*)&Bs[buf][k][tx * 4];
            ulonglong2 q1 = *(const ulonglong2*)&Bs[buf][k][64 + tx * 4];
            unsigned long long bp[4] = {q0.x, q0.y, q1.x, q1.y};
            float4 a0 = *(const float4*)&As[buf][k][ty * 4];
            float4 a1 = *(const float4*)&As[buf][k][64 + ty * 4];
            float aa[8] = {a0.x, a0.y, a0.z, a0.w, a1.x, a1.y, a1.z, a1.w};
#pragma unroll
            for (int i = 0; i < 8; i++) {
                unsigned long long ad = pack2(aa[i], aa[i]);
#pragma unroll
                for (int j = 0; j < 4; j++) ffma2(acc2[i][j], ad, bp[j]);
            }
        }
        if (kc + 1 < KC) {
            int nb = buf ^ 1;
            As[nb][ahalf * 4 + 0][arow] = ra.x; As[nb][ahalf * 4 + 1][arow] = ra.y;
            As[nb][ahalf * 4 + 2][arow] = ra.z; As[nb][ahalf * 4 + 3][arow] = ra.w;
            Bs[nb][ahalf * 4 + 0][arow] = rb.x; Bs[nb][ahalf * 4 + 1][arow] = rb.y;
            Bs[nb][ahalf * 4 + 2][arow] = rb.z; Bs[nb][ahalf * 4 + 3][arow] = rb.w;
            __syncthreads();
            buf = nb;
        }
    }

#pragma unroll
    for (int i = 0; i < 8; i++) {
        int m = m0 + ((i < 4) ? (ty * 4 + i) : (64 + ty * 4 + (i - 4)));
        float2 p0 = unpack2(acc2[i][0]), p1 = unpack2(acc2[i][1]);
        float2 p2 = unpack2(acc2[i][2]), p3 = unpack2(acc2[i][3]);
        float4 h0 = *(const float4*)&hio[(size_t)m * 128 + tx * 4];
        float4 h1 = *(const float4*)&hio[(size_t)m * 128 + 64 + tx * 4];
        float x[8];
        x[0] = p0.x + bias[tx * 4 + 0] + h0.x;
        x[1] = p0.y + bias[tx * 4 + 1] + h0.y;
        x[2] = p1.x + bias[tx * 4 + 2] + h0.z;
        x[3] = p1.y + bias[tx * 4 + 3] + h0.w;
        x[4] = p2.x + bias[64 + tx * 4 + 0] + h1.x;
        x[5] = p2.y + bias[64 + tx * 4 + 1] + h1.y;
        x[6] = p3.x + bias[64 + tx * 4 + 2] + h1.z;
        x[7] = p3.y + bias[64 + tx * 4 + 3] + h1.w;
        float s = 0.f;
#pragma unroll
        for (int j = 0; j < 8; j++) s += x[j];
#pragma unroll
        for (int off = 1; off < 16; off <<= 1)
            s += __shfl_xor_sync(0xffffffffu, s, off);
        float mean = s * 0.0078125f;
        float c[8], v = 0.f;
#pragma unroll
        for (int j = 0; j < 8; j++) { c[j] = x[j] - mean; v += c[j] * c[j]; }
#pragma unroll
        for (int off = 1; off < 16; off <<= 1)
            v += __shfl_xor_sync(0xffffffffu, v, off);
        float den = sqrtf(v * 0.0078125f + 1e-5f);
        float4 o0, o1;
        o0.x = c[0] / den * gamma[tx * 4 + 0] + beta[tx * 4 + 0];
        o0.y = c[1] / den * gamma[tx * 4 + 1] + beta[tx * 4 + 1];
        o0.z = c[2] / den * gamma[tx * 4 + 2] + beta[tx * 4 + 2];
        o0.w = c[3] / den * gamma[tx * 4 + 3] + beta[tx * 4 + 3];
        o1.x = c[4] / den * gamma[64 + tx * 4 + 0] + beta[64 + tx * 4 + 0];
        o1.y = c[5] / den * gamma[64 + tx * 4 + 1] + beta[64 + tx * 4 + 1];
        o1.z = c[6] / den * gamma[64 + tx * 4 + 2] + beta[64 + tx * 4 + 2];
        o1.w = c[7] / den * gamma[64 + tx * 4 + 3] + beta[64 + tx * 4 + 3];
        *(float4*)&hio[(size_t)m * 128 + tx * 4] = o0;
        *(float4*)&hio[(size_t)m * 128 + 64 + tx * 4] = o1;
    }
}

// ---------------- SGEMM 64x128, occ-3 (small GEMMs, single wave) ----------------
__global__ void __launch_bounds__(256, 3)
gemm64(const float* __restrict__ A, const float* __restrict__ W,
       const float* __restrict__ bias, float* __restrict__ C,
       int Nout, int K, int ldw, int relu) {
    __shared__ float As[2][8][64];
    __shared__ float Bs[2][8][128];
    const int tid = threadIdx.x;
    const int tx = tid & 15, ty = tid >> 4;
    const int m0 = blockIdx.y * 64, n0 = blockIdx.x * 128;
    unsigned long long acc2[4][4];
#pragma unroll
    for (int i = 0; i < 4; i++)
#pragma unroll
        for (int j = 0; j < 4; j++) acc2[i][j] = 0ull;

    const int arow = tid >> 1, ahalf = tid & 1;
    const bool aload = tid < 128;
    const float* Aptr = A + (size_t)(m0 + (aload ? arow : 0)) * K + ahalf * 4;
    const float* Wptr = W + (size_t)(n0 + arow) * ldw + ahalf * 4;

    const int KC = K >> 3;
    float4 ra = make_float4(0.f, 0.f, 0.f, 0.f), rb;
    if (aload) ra = *(const float4*)(Aptr);
    rb = *(const float4*)(Wptr);
    if (aload) {
        As[0][ahalf * 4 + 0][arow] = ra.x; As[0][ahalf * 4 + 1][arow] = ra.y;
        As[0][ahalf * 4 + 2][arow] = ra.z; As[0][ahalf * 4 + 3][arow] = ra.w;
    }
    Bs[0][ahalf * 4 + 0][arow] = rb.x; Bs[0][ahalf * 4 + 1][arow] = rb.y;
    Bs[0][ahalf * 4 + 2][arow] = rb.z; Bs[0][ahalf * 4 + 3][arow] = rb.w;
    __syncthreads();

    int buf = 0;
    for (int kc = 0; kc < KC; kc++) {
        if (kc + 1 < KC) {
            if (aload) ra = *(const float4*)(Aptr + (kc + 1) * 8);
            rb = *(const float4*)(Wptr + (kc + 1) * 8);
        }
#pragma unroll
        for (int k = 0; k < 8; k++) {
            ulonglong2 q0 = *(const ulonglong2*)&Bs[buf][k][tx * 4];
            ulonglong2 q1 = *(const ulonglong2*)&Bs[buf][k][64 + tx * 4];
            unsigned long long bp[4] = {q0.x, q0.y, q1.x, q1.y};
            float4 a0 = *(const float4*)&As[buf][k][ty * 4];
            float aa[4] = {a0.x, a0.y, a0.z, a0.w};
#pragma unroll
            for (int i = 0; i < 4; i++) {
                unsigned long long ad = pack2(aa[i], aa[i]);
#pragma unroll
                for (int j = 0; j < 4; j++) ffma2(acc2[i][j], ad, bp[j]);
            }
        }
        if (kc + 1 < KC) {
            int nb = buf ^ 1;
            if (aload) {
                As[nb][ahalf * 4 + 0][arow] = ra.x; As[nb][ahalf * 4 + 1][arow] = ra.y;
                As[nb][ahalf * 4 + 2][arow] = ra.z; As[nb][ahalf * 4 + 3][arow] = ra.w;
            }
            Bs[nb][ahalf * 4 + 0][arow] = rb.x; Bs[nb][ahalf * 4 + 1][arow] = rb.y;
            Bs[nb][ahalf * 4 + 2][arow] = rb.z; Bs[nb][ahalf * 4 + 3][arow] = rb.w;
            __syncthreads();
            buf = nb;
        }
    }

    float bv[8];
#pragma unroll
    for (int j = 0; j < 4; j++) {
        bv[j]     = bias ? bias[n0 + tx * 4 + j]      : 0.f;
        bv[4 + j] = bias ? bias[n0 + 64 + tx * 4 + j] : 0.f;
    }
#pragma unroll
    for (int i = 0; i < 4; i++) {
        int m = m0 + ty * 4 + i;
        float2 p0 = unpack2(acc2[i][0]), p1 = unpack2(acc2[i][1]);
        float2 p2 = unpack2(acc2[i][2]), p3 = unpack2(acc2[i][3]);
        float4 o0, o1;
        o0.x = p0.x + bv[0]; o0.y = p0.y + bv[1]; o0.z = p1.x + bv[2]; o0.w = p1.y + bv[3];
        o1.x = p2.x + bv[4]; o1.y = p2.y + bv[5]; o1.z = p3.x + bv[6]; o1.w = p3.y + bv[7];
        if (relu) {
            o0.x = fmaxf(o0.x, 0.f); o0.y = fmaxf(o0.y, 0.f);
            o0.z = fmaxf(o0.z, 0.f); o0.w = fmaxf(o0.w, 0.f);
            o1.x = fmaxf(o1.x, 0.f); o1.y = fmaxf(o1.y, 0.f);
            o1.z = fmaxf(o1.z, 0.f); o1.w = fmaxf(o1.w, 0.f);
        }
        *(float4*)&C[(size_t)m * Nout + n0 + tx * 4] = o0;
        *(float4*)&C[(size_t)m * Nout + n0 + 64 + tx * 4] = o1;
    }
}

// ---------------- batched bounded GEMM (S1) ----------------
__global__ void __launch_bounds__(256, 3)
gemm_batched(const float* __restrict__ A0, const float* __restrict__ W0,
             float* __restrict__ C0, int M, int Nout, int K,
             long long sA, long long sW, long long sC) {
    __shared__ float As[2][8][64];
    __shared__ float Bs[2][8][128];
    const float* A = A0 + (long long)blockIdx.z * sA;
    const float* W = W0 + (long long)blockIdx.z * sW;
    float* C = C0 + (long long)blockIdx.z * sC;
    const int tid = threadIdx.x;
    const int tx = tid & 15, ty = tid >> 4;
    const int m0 = blockIdx.y * 64, n0 = blockIdx.x * 128;
    unsigned long long acc2[4][4];
#pragma unroll
    for (int i = 0; i < 4; i++)
#pragma unroll
        for (int j = 0; j < 4; j++) acc2[i][j] = 0ull;

    const int arow = tid >> 1, ahalf = tid & 1;
    const bool aload = tid < 128;
    const bool aok = aload && (m0 + arow < M);
    const bool wok = (n0 + arow < Nout);
    const float* Aptr = A + (size_t)(aok ? (m0 + arow) : 0) * K + ahalf * 4;
    const float* Wptr = W + (size_t)(wok ? (n0 + arow) : 0) * K + ahalf * 4;

    const int KC = K >> 3;
    float4 ra = make_float4(0.f, 0.f, 0.f, 0.f), rb;
    if (aload) ra = *(const float4*)(Aptr);
    rb = *(const float4*)(Wptr);
    if (aload) {
        As[0][ahalf * 4 + 0][arow] = ra.x; As[0][ahalf * 4 + 1][arow] = ra.y;
        As[0][ahalf * 4 + 2][arow] = ra.z; As[0][ahalf * 4 + 3][arow] = ra.w;
    }
    Bs[0][ahalf * 4 + 0][arow] = rb.x; Bs[0][ahalf * 4 + 1][arow] = rb.y;
    Bs[0][ahalf * 4 + 2][arow] = rb.z; Bs[0][ahalf * 4 + 3][arow] = rb.w;
    __syncthreads();

    int buf = 0;
    for (int kc = 0; kc < KC; kc++) {
        if (kc + 1 < KC) {
            if (aload) ra = *(const float4*)(Aptr + (kc + 1) * 8);
            rb = *(const float4*)(Wptr + (kc + 1) * 8);
        }
#pragma unroll
        for (int k = 0; k < 8; k++) {
            ulonglong2 q0 = *(const ulonglong2*)&Bs[buf][k][tx * 4];
            ulonglong2 q1 = *(const ulonglong2*)&Bs[buf][k][64 + tx * 4];
            unsigned long long bp[4] = {q0.x, q0.y, q1.x, q1.y};
            float4 a0 = *(const float4*)&As[buf][k][ty * 4];
            float aa[4] = {a0.x, a0.y, a0.z, a0.w};
#pragma unroll
            for (int i = 0; i < 4; i++) {
                unsigned long long ad = pack2(aa[i], aa[i]);
#pragma unroll
                for (int j = 0; j < 4; j++) ffma2(acc2[i][j], ad, bp[j]);
            }
        }
        if (kc + 1 < KC) {
            int nb = buf ^ 1;
            if (aload) {
                As[nb][ahalf * 4 + 0][arow] = ra.x; As[nb][ahalf * 4 + 1][arow] = ra.y;
                As[nb][ahalf * 4 + 2][arow] = ra.z; As[nb][ahalf * 4 + 3][arow] = ra.w;
            }
            Bs[nb][ahalf * 4 + 0][arow] = rb.x; Bs[nb][ahalf * 4 + 1][arow] = rb.y;
            Bs[nb][ahalf * 4 + 2][arow] = rb.z; Bs[nb][ahalf * 4 + 3][arow] = rb.w;
            __syncthreads();
            buf = nb;
        }
    }

#pragma unroll
    for (int i = 0; i < 4; i++) {
        int m = m0 + ty * 4 + i;
        if (m >= M) continue;
        float2 p0 = unpack2(acc2[i][0]), p1 = unpack2(acc2[i][1]);
        float2 p2 = unpack2(acc2[i][2]), p3 = unpack2(acc2[i][3]);
        int c0 = n0 + tx * 4, c1 = n0 + 64 + tx * 4;
        if (c0 + 3 < Nout) {
            float4 o; o.x = p0.x; o.y = p0.y; o.z = p1.x; o.w = p1.y;
            *(float4*)&C[(size_t)m * Nout + c0] = o;
        }
        if (c1 + 3 < Nout) {
            float4 o; o.x = p2.x; o.y = p2.y; o.z = p3.x; o.w = p3.y;
            *(float4*)&C[(size_t)m * Nout + c1] = o;
        }
    }
}

// ---------------- attention ----------------
__global__ void __launch_bounds__(256)
attention_smem(const float* __restrict__ qkv, float* __restrict__ out) {
    int bh = blockIdx.x;
    int b = bh >> 3, h = bh & 7;
    __shared__ float QsT[DH_][208], KsT[DH_][208], VsT[DH_][208];
    const float* base = qkv + (size_t)b * N_ * 384 + h * DH_;
    int tid = threadIdx.x;
    for (int i = tid; i < N_ * DH_; i += 256) {
        int n = i >> 4, d = i & 15;
        const float* rp = base + (size_t)n * 384 + d;
        QsT[d][n] = rp[0];
        KsT[d][n] = rp[128];
        VsT[d][n] = rp[256];
    }
    __syncthreads();
    int warp = tid >> 5, lane = tid & 31;
    for (int q = warp; q < N_; q += 8) {
        float qv[DH_];
#pragma unroll
        for (int d = 0; d < DH_; d++) qv[d] = QsT[d][q];
        float s[7];
        float mx = -INFINITY;
#pragma unroll
        for (int j = 0; j < 7; j++) {
            int k = lane + 32 * j;
            float a = 0.f;
            if (k < N_) {
#pragma unroll
                for (int d = 0; d < DH_; d++) a += qv[d] * KsT[d][k];
                a *= 0.25f;
            } else a = -INFINITY;
            s[j] = a;
            mx = fmaxf(mx, a);
        }
#pragma unroll
        for (int off = 16; off; off >>= 1)
            mx = fmaxf(mx, __shfl_xor_sync(0xffffffffu, mx, off));
        float p[7];
        float sum = 0.f;
#pragma unroll
        for (int j = 0; j < 7; j++) {
            int k = lane + 32 * j;
            p[j] = (k < N_) ? expf(s[j] - mx) : 0.f;
            sum += p[j];
        }
#pragma unroll
        for (int off = 16; off; off >>= 1)
            sum += __shfl_xor_sync(0xffffffffu, sum, off);
        float inv = 1.f / sum;
        float o[DH_];
#pragma unroll
        for (int d = 0; d < DH_; d++) o[d] = 0.f;
#pragma unroll
        for (int j = 0; j < 7; j++) {
            int k = lane + 32 * j;
            if (k < N_) {
                float wgt = p[j] * inv;
#pragma unroll
                for (int d = 0; d < DH_; d++) o[d] += wgt * VsT[d][k];
            }
        }
#pragma unroll
        for (int d = 0; d < DH_; d++) {
            float v = o[d];
#pragma unroll
            for (int off = 16; off; off >>= 1)
                v += __shfl_xor_sync(0xffffffffu, v, off);
            if (lane == d)
                out[((size_t)b * N_ + q) * D_ + h * DH_ + d] = v;
        }
    }
}

// ---------------- small precompute kernels ----------------
__global__ void compute_M_kernel(const float* __restrict__ Wq, const float* __restrict__ Wctx) {
    int d = blockIdx.y;
    int c = blockIdx.x * blockDim.x + threadIdx.x;
    if (c >= 3 * D_) return;
    float acc = 0.f;
    for (int k = 0; k < D_; k++) acc += Wq[d * D_ + k] * Wctx[k * (3 * D_) + c];
    g_M[d * (3 * D_) + c] = acc;
}

__global__ void compute_vecs_kernel(const float* __restrict__ Wq, const float* __restrict__ bctx,
                                    const float* __restrict__ Wcap, const float* __restrict__ bcap) {
    int d = threadIdx.x;
    float a = 0.f, u = 0.f, bq = 0.f;
    for (int k = 0; k < D_; k++) {
        float m = g_M[d * (3 * D_) + 2 * D_ + k];
        a += m * bcap[k];
        u += m * Wcap[k];
        bq += Wq[d * D_ + k] * bctx[k];
    }
    g_vconst[d] = a + bq;
    g_vu[d] = u;
}

__global__ void compute_gctx_kernel() {
    int b = blockIdx.x, d = threadIdx.x;
    float s = 0.f;
    for (int n = 0; n < N_; n++) s += g_h[((size_t)b * N_ + n) * D_ + d];
    g_gctx[b * D_ + d] = s / (float)N_;
}

__global__ void compute_qctx_kernel() {
    int b = blockIdx.x, d = threadIdx.x;
    float a = g_vconst[d];
    for (int k = 0; k < D_; k++) a += g_M[d * (3 * D_) + D_ + k] * g_gctx[b * D_ + k];
    g_qctx[b * D_ + d] = a;
}

__global__ void compute_CU_kernel() {
    int i = blockIdx.x * blockDim.x + threadIdx.x;
    if (i >= ROWS) return;
    int b = i / N_;
    const float* kr = g_kmat + (size_t)i * D_;
    float c = 0.f, u = 0.f;
    for (int d = 0; d < D_; d++) {
        c += kr[d] * g_qctx[b * D_ + d];
        u += kr[d] * g_vu[d];
    }
    g_C[i] = c;
    g_U[i] = u;
}

// ---------------- decode: one warp per batch ----------------
__device__ __forceinline__ float pick7(const float a[7], int s) {
    float r = a[0];
    if (s == 1) r = a[1];
    if (s == 2) r = a[2];
    if (s == 3) r = a[3];
    if (s == 4) r = a[4];
    if (s == 5) r = a[5];
    if (s == 6) r = a[6];
    return r;
}

__global__ void __launch_bounds__(32)
decode_warp(float* __restrict__ path_out, float* __restrict__ lp_out) {
    const unsigned FULL = 0xffffffffu;
    int b = blockIdx.x;
    int lane = threadIdx.x;
    float drv[7], Cv[7], Uv[7], s1[7], gum[7];
    unsigned vism = 0;
#pragma unroll
    for (int j = 0; j < 7; j++) {
        int n = lane + 32 * j;
        if (n < N_) {
            drv[j] = g_dr[b * N_ + n];
            Cv[j] = g_C[b * N_ + n];
            Uv[j] = g_U[b * N_ + n];
            s1[j] = g_S1[(size_t)(b * N_) * N_ + n];
            gum[j] = g_gum[(size_t)b * N_ + n];
        } else { drv[j] = 0.f; Cv[j] = 0.f; Uv[j] = 0.f; s1[j] = 0.f; gum[j] = 0.f; }
    }
    float rem = 1.0f, acc = 0.f;
    int cur = 0, cnt = N_ - 1;
    bool done = false;
    if (lane == 0) path_out[(size_t)b * (STEPS + 1)] = 0.0f;

    for (int step = 0; step < STEPS; step++) {
        bool anyf = false, anyu = false;
#pragma unroll
        for (int j = 0; j < 7; j++) {
            int n = lane + 32 * j;
            bool valid = (n >= 1) && (n < N_);
            bool vis = (vism >> j) & 1u;
            if (valid && !vis) {
                anyu = true;
                if (drv[j] <= rem) anyf = true;
            }
        }
        bool has_feas = __any_sync(FULL, anyf);
        bool all_served = !__any_sync(FULL, anyu);

        bool at_depot = (cur == 0) && !done;
        bool not_depot = (cur != 0) && !done;
        bool depot_mask = (at_depot && has_feas) ||
                          (not_depot && has_feas && !all_served);
        bool force_depot = (all_served && (cur != 0) && !done) ||
                           (not_depot && !has_feas) || done;

        float mloc[7];
        float lmax = -INFINITY, lkey = -INFINITY;
        int lidx = 1000;
#pragma unroll
        for (int j = 0; j < 7; j++) {
            int n = lane + 32 * j;
            if (n < N_) {
                bool vis = (vism >> j) & 1u;
                bool infeas = vis || (drv[j] > rem);
                if (n == 0) infeas = infeas || depot_mask;
                float logit = (s1[j] + Cv[j] + rem * Uv[j]) / SQRTD;
                float m = infeas ? -1e9f : logit;
                mloc[j] = m;
                float k = m + gum[j];
                lmax = fmaxf(lmax, m);
                if (k > lkey) { lkey = k; lidx = n; }
            } else mloc[j] = -INFINITY;
        }
        float kv = lkey, mx = lmax;
        int ki = lidx;
#pragma unroll
        for (int off = 16; off; off >>= 1) {
            mx = fmaxf(mx, __shfl_xor_sync(FULL, mx, off));
            float kv2 = __shfl_xor_sync(FULL, kv, off);
            int ki2 = __shfl_xor_sync(FULL, ki, off);
            if (kv2 > kv || (kv2 == kv && ki2 < ki)) { kv = kv2; ki = ki2; }
        }
        int sel = force_depot ? 0 : ki;
        float s1n[7], gumn[7];
        if (step + 1 < STEPS) {
#pragma unroll
            for (int j = 0; j < 7; j++) {
                int n = lane + 32 * j;
                if (n < N_) {
                    s1n[j] = g_S1[(size_t)(b * N_ + sel) * N_ + n];
                    gumn[j] = g_gum[(size_t)(step + 1) * ROWS + b * N_ + n];
                } else { s1n[j] = 0.f; gumn[j] = 0.f; }
            }
        }
        float e = 0.f;
#pragma unroll
        for (int j = 0; j < 7; j++) {
            int n = lane + 32 * j;
            if (n < N_) e += expf(mloc[j] - mx);
        }
#pragma unroll
        for (int off = 16; off; off >>= 1)
            e += __shfl_xor_sync(FULL, e, off);

        int slot = sel >> 5, owner = sel & 31;
        float msel = __shfl_sync(FULL, pick7(mloc, slot), owner);
        float dsel = __shfl_sync(FULL, pick7(drv, slot), owner);
        unsigned vsel = __shfl_sync(FULL, (vism >> slot) & 1u, owner);
        float slp = force_depot ? 0.f : (msel - mx - logf(e));
        bool isd = (sel == 0);
        float nr = isd ? 1.0f : (rem - dsel);
        rem = fminf(fmaxf(nr, 0.f), 1.f);
        if (!isd && !vsel) {
            cnt--;
            if (lane == owner) vism |= 1u << slot;
        }
        cur = sel;
        done = done || (cnt == 0 && isd);
        acc += slp;
        if (lane == 0) path_out[(size_t)b * (STEPS + 1) + 1 + step] = (float)sel;
#pragma unroll
        for (int j = 0; j < 7; j++) { s1[j] = s1n[j]; gum[j] = gumn[j]; }
    }
    if (lane == 0 && lp_out) lp_out[b] = acc;
}

// ---------------- launch ----------------
extern "C" void kernel_launch(void* const* d_in, const int* in_sizes, int n_in,
                              void* d_out, int out_size) {
    int perm[23];
    for (int i = 0; i < 23; i++) perm[i] = i;
    if (n_in >= 23 && in_sizes[0] == 786432) {
        const int m[23] = {15,16,14,17,18,7,13,5,12,0,8,1,9,20,19,22,21,6,4,2,10,3,11};
        for (int i = 0; i < 23; i++) perm[i] = m[i];
    }
    const float* coords   = (const float*)d_in[perm[0]];
    const float* demands  = (const float*)d_in[perm[1]];
    const float* capacity = (const float*)d_in[perm[2]];
    const float* embed_W  = (const float*)d_in[perm[3]];
    const float* embed_b  = (const float*)d_in[perm[4]];
    const float* Wqkv     = (const float*)d_in[perm[5]];
    const float* bqkv     = (const float*)d_in[perm[6]];
    const float* Wo       = (const float*)d_in[perm[7]];
    const float* bo       = (const float*)d_in[perm[8]];
    const float* W1       = (const float*)d_in[perm[9]];
    const float* b1       = (const float*)d_in[perm[10]];
    const float* W2       = (const float*)d_in[perm[11]];
    const float* b2       = (const float*)d_in[perm[12]];
    const float* ln1_g    = (const float*)d_in[perm[13]];
    const float* ln1_b    = (const float*)d_in[perm[14]];
    const float* ln2_g    = (const float*)d_in[perm[15]];
    const float* ln2_b    = (const float*)d_in[perm[16]];
    const float* Wq       = (const float*)d_in[perm[17]];
    const float* Wk       = (const float*)d_in[perm[18]];
    const float* Wcap     = (const float*)d_in[perm[19]];
    const float* bcap     = (const float*)d_in[perm[20]];
    const float* Wctx     = (const float*)d_in[perm[21]];
    const float* bctx     = (const float*)d_in[perm[22]];

    float *g_h_p, *g_qkv_p, *g_att_p, *g_ffn_p, *g_kmat_p, *g_hM_p, *g_S1_p, *g_M_p;
    cudaGetSymbolAddress((void**)&g_h_p, g_h);
    cudaGetSymbolAddress((void**)&g_qkv_p, g_qkv);
    cudaGetSymbolAddress((void**)&g_att_p, g_att);
    cudaGetSymbolAddress((void**)&g_ffn_p, g_ffn);
    cudaGetSymbolAddress((void**)&g_kmat_p, g_kmat);
    cudaGetSymbolAddress((void**)&g_hM_p, g_hM);
    cudaGetSymbolAddress((void**)&g_S1_p, g_S1);
    cudaGetSymbolAddress((void**)&g_M_p, g_M);

    embed_kernel<<<ROWS, 128>>>(coords, demands, capacity, embed_W, embed_b);
    make_keys_kernel<<<1, 1>>>();
    gumbel_kernel<<<dim3(100, STEPS), 256>>>();

    for (int i = 0; i < L_; i++) {
        // QKV: 25600 x 384, K=128  (MT=128, best AI)
        gemm128<<<dim3(3, 200), 256>>>(
            g_h_p, Wqkv + (size_t)i * 384 * 128, bqkv + i * 384, g_qkv_p,
            384, 128, 128, 0);
        attention_smem<<<B_ * H_, 256>>>(g_qkv_p, g_att_p);
        // Wo + residual + LN1 (MT=128, 200 blocks = single wave)
        gemm_ln128<<<dim3(1, 200), 256>>>(
            g_att_p, Wo + (size_t)i * 128 * 128, bo + i * 128, g_h_p,
            ln1_g + i * 128, ln1_b + i * 128, 128);
        // FFN1: 25600 x 2048, K=128, relu (MT=128)
        gemm128<<<dim3(16, 200), 256>>>(
            g_h_p, W1 + (size_t)i * F_ * 128, b1 + i * F_, g_ffn_p,
            F_, 128, 128, 1);
        // FFN2 + residual + LN2 (K=2048, MT=128, single wave)
        gemm_ln128<<<dim3(1, 200), 256>>>(
            g_ffn_p, W2 + (size_t)i * 128 * F_, b2 + i * 128, g_h_p,
            ln2_g + i * 128, ln2_b + i * 128, F_);
    }

    compute_gctx_kernel<<<B_, 128>>>();
    compute_M_kernel<<<dim3(3, 128), 128>>>(Wq, Wctx);
    compute_vecs_kernel<<<1, 128>>>(Wq, bctx, Wcap, bcap);
    compute_qctx_kernel<<<B_, 128>>>();
    gemm64<<<dim3(1, 400), 256>>>(g_h_p, Wk, nullptr, g_kmat_p, 128, 128, 128, 0);
    gemm64<<<dim3(1, 400), 256>>>(g_h_p, g_M_p, nullptr, g_hM_p, 128, 128, 384, 0);
    gemm_batched<<<dim3(2, 4, B_), 256>>>(
        g_hM_p, g_kmat_p, g_S1_p, N_, N_, 128,
        (long long)N_ * 128, (long long)N_ * 128, (long long)N_ * N_);
    compute_CU_kernel<<<(ROWS + 255) / 256, 256>>>();

    float* out_f = (float*)d_out;
    float* lp_out = (out_size >= B_ * (STEPS + 1) + B_) ? (out_f + B_ * (STEPS + 1)) : nullptr;
    decode_warp<<<B_, 32>>>(out_f, lp_out);
}

// round 8
// speedup vs baseline: 1.0920x; 1.0080x over previous
#include <cuda_runtime.h>
#include <stdint.h>
#include <math.h>

// ---------------- problem constants ----------------
static constexpr int B_ = 128, N_ = 200, D_ = 128, H_ = 8, DH_ = 16, L_ = 3, F_ = 2048;
static constexpr int ROWS = B_ * N_;            // 25600
static constexpr int STEPS = 2 * (N_ - 1) + 1;  // 399
static constexpr float SQRTD = 11.313708498984761f;

// ---------------- scratch ----------------
__device__ float g_h[ROWS * D_];
__device__ float g_qkv[ROWS * 3 * D_];
__device__ float g_att[ROWS * D_];
__device__ float g_ffn[ROWS * F_];
__device__ float g_kmat[ROWS * D_];
__device__ float g_hM[ROWS * D_];
__device__ float g_S1[B_ * N_ * N_];
__device__ float g_dr[ROWS];
__device__ float g_gctx[B_ * D_];
__device__ float g_M[D_ * 3 * D_];
__device__ float g_vconst[D_];
__device__ float g_vu[D_];
__device__ float g_qctx[B_ * D_];
__device__ float g_C[ROWS];
__device__ float g_U[ROWS];

// ---------------- compile-time threefry key chain (key(42) is constant!) ----------------
struct U2c { uint32_t a, b; };
constexpr uint32_t crotl(uint32_t v, int d) { return (v << d) | (v >> (32 - d)); }
constexpr U2c ctf(uint32_t k0, uint32_t k1, uint32_t x0, uint32_t x1) {
    uint32_t ks2 = k0 ^ k1 ^ 0x1BD11BDAu;
    x0 += k0; x1 += k1;
    const int r0[4] = {13, 15, 26, 6};
    const int r1[4] = {17, 29, 16, 24};
    for (int i = 0; i < 4; i++) { x0 += x1; x1 = crotl(x1, r0[i]); x1 ^= x0; }
    x0 += k1; x1 += ks2 + 1u;
    for (int i = 0; i < 4; i++) { x0 += x1; x1 = crotl(x1, r1[i]); x1 ^= x0; }
    x0 += ks2; x1 += k0 + 2u;
    for (int i = 0; i < 4; i++) { x0 += x1; x1 = crotl(x1, r0[i]); x1 ^= x0; }
    x0 += k0; x1 += k1 + 3u;
    for (int i = 0; i < 4; i++) { x0 += x1; x1 = crotl(x1, r1[i]); x1 ^= x0; }
    x0 += k1; x1 += ks2 + 4u;
    for (int i = 0; i < 4; i++) { x0 += x1; x1 = crotl(x1, r0[i]); x1 ^= x0; }
    x0 += ks2; x1 += k0 + 5u;
    return {x0, x1};
}
struct KeysCT { uint32_t x[STEPS]; uint32_t y[STEPS]; };
constexpr KeysCT make_keys_ct() {
    KeysCT K{};
    uint32_t k0 = 0u, k1 = 42u;  // jax.random.key(42)
    for (int t = 0; t < STEPS; t++) {
        U2c nk = ctf(k0, k1, 0u, 0u);   // partitionable split: key'
        U2c sk = ctf(k0, k1, 0u, 1u);   // subkey
        K.x[t] = sk.a; K.y[t] = sk.b;
        k0 = nk.a; k1 = nk.b;
    }
    return K;
}
__constant__ KeysCT c_keys = make_keys_ct();

// ---------------- f32x2 helpers ----------------
__device__ __forceinline__ void ffma2(unsigned long long& d, unsigned long long a,
                                      unsigned long long b) {
    asm("fma.rn.f32x2 %0, %1, %2, %0;" : "+l"(d) : "l"(a), "l"(b));
}
__device__ __forceinline__ unsigned long long pack2(float lo, float hi) {
    unsigned long long r;
    asm("mov.b64 %0, {%1, %2};" : "=l"(r) : "f"(lo), "f"(hi));
    return r;
}
__device__ __forceinline__ float2 unpack2(unsigned long long v) {
    float2 r;
    asm("mov.b64 {%0, %1}, %2;" : "=f"(r.x), "=f"(r.y) : "l"(v));
    return r;
}

// ---------------- threefry2x32 (exact JAX), runtime ----------------
__device__ __forceinline__ uint32_t rotl32(uint32_t x, int d) {
    return (x << d) | (x >> (32 - d));
}
__device__ __forceinline__ uint2 threefry2x32(uint32_t k0, uint32_t k1,
                                              uint32_t x0, uint32_t x1) {
    uint32_t ks2 = k0 ^ k1 ^ 0x1BD11BDAu;
    x0 += k0; x1 += k1;
    const int r0[4] = {13, 15, 26, 6};
    const int r1[4] = {17, 29, 16, 24};
#pragma unroll
    for (int i = 0; i < 4; i++) { x0 += x1; x1 = rotl32(x1, r0[i]); x1 ^= x0; }
    x0 += k1; x1 += ks2 + 1u;
#pragma unroll
    for (int i = 0; i < 4; i++) { x0 += x1; x1 = rotl32(x1, r1[i]); x1 ^= x0; }
    x0 += ks2; x1 += k0 + 2u;
#pragma unroll
    for (int i = 0; i < 4; i++) { x0 += x1; x1 = rotl32(x1, r0[i]); x1 ^= x0; }
    x0 += k0; x1 += k1 + 3u;
#pragma unroll
    for (int i = 0; i < 4; i++) { x0 += x1; x1 = rotl32(x1, r1[i]); x1 ^= x0; }
    x0 += k1; x1 += ks2 + 4u;
#pragma unroll
    for (int i = 0; i < 4; i++) { x0 += x1; x1 = rotl32(x1, r0[i]); x1 ^= x0; }
    x0 += ks2; x1 += k0 + 5u;
    return make_uint2(x0, x1);
}

// ---------------- embed ----------------
__global__ void embed_kernel(const float* __restrict__ coords,
                             const float* __restrict__ demands,
                             const float* __restrict__ cap,
                             const float* __restrict__ W,
                             const float* __restrict__ bias) {
    int row = blockIdx.x;
    int d = threadIdx.x;
    int b = row / N_;
    float cx = coords[row * 2 + 0];
    float cy = coords[row * 2 + 1];
    float r = demands[row] / cap[b];
    if (d == 0) g_dr[row] = r;
    float v = W[d * 3 + 0] * cx + W[d * 3 + 1] * cy + W[d * 3 + 2] * r + bias[d];
    g_h[(size_t)row * D_ + d] = v;
}

// ---------------- SGEMM 128x128 tile, occ-2: C = A @ W^T (+bias)(+relu) ----------------
__global__ void __launch_bounds__(256, 2)
gemm128(const float* __restrict__ A, const float* __restrict__ W,
        const float* __restrict__ bias, float* __restrict__ C,
        int Nout, int K, int ldw, int relu) {
    __shared__ float As[2][8][128];
    __shared__ float Bs[2][8][128];
    const int tid = threadIdx.x;
    const int tx = tid & 15, ty = tid >> 4;
    const int m0 = blockIdx.y * 128, n0 = blockIdx.x * 128;
    unsigned long long acc2[8][4];
#pragma unroll
    for (int i = 0; i < 8; i++)
#pragma unroll
        for (int j = 0; j < 4; j++) acc2[i][j] = 0ull;

    const int arow = tid >> 1, ahalf = tid & 1;
    const float* Aptr = A + (size_t)(m0 + arow) * K + ahalf * 4;
    const float* Wptr = W + (size_t)(n0 + arow) * ldw + ahalf * 4;

    const int KC = K >> 3;
    float4 ra = *(const float4*)(Aptr);
    float4 rb = *(const float4*)(Wptr);
    As[0][ahalf * 4 + 0][arow] = ra.x; As[0][ahalf * 4 + 1][arow] = ra.y;
    As[0][ahalf * 4 + 2][arow] = ra.z; As[0][ahalf * 4 + 3][arow] = ra.w;
    Bs[0][ahalf * 4 + 0][arow] = rb.x; Bs[0][ahalf * 4 + 1][arow] = rb.y;
    Bs[0][ahalf * 4 + 2][arow] = rb.z; Bs[0][ahalf * 4 + 3][arow] = rb.w;
    __syncthreads();

    int buf = 0;
    for (int kc = 0; kc < KC; kc++) {
        if (kc + 1 < KC) {
            ra = *(const float4*)(Aptr + (kc + 1) * 8);
            rb = *(const float4*)(Wptr + (kc + 1) * 8);
        }
#pragma unroll
        for (int k = 0; k < 8; k++) {
            ulonglong2 q0 = *(const ulonglong2*)&Bs[buf][k][tx * 4];
            ulonglong2 q1 = *(const ulonglong2*)&Bs[buf][k][64 + tx * 4];
            unsigned long long bp[4] = {q0.x, q0.y, q1.x, q1.y};
            float4 a0 = *(const float4*)&As[buf][k][ty * 4];
            float4 a1 = *(const float4*)&As[buf][k][64 + ty * 4];
            float aa[8] = {a0.x, a0.y, a0.z, a0.w, a1.x, a1.y, a1.z, a1.w};
#pragma unroll
            for (int i = 0; i < 8; i++) {
                unsigned long long ad = pack2(aa[i], aa[i]);
#pragma unroll
                for (int j = 0; j < 4; j++) ffma2(acc2[i][j], ad, bp[j]);
            }
        }
        if (kc + 1 < KC) {
            int nb = buf ^ 1;
            As[nb][ahalf * 4 + 0][arow] = ra.x; As[nb][ahalf * 4 + 1][arow] = ra.y;
            As[nb][ahalf * 4 + 2][arow] = ra.z; As[nb][ahalf * 4 + 3][arow] = ra.w;
            Bs[nb][ahalf * 4 + 0][arow] = rb.x; Bs[nb][ahalf * 4 + 1][arow] = rb.y;
            Bs[nb][ahalf * 4 + 2][arow] = rb.z; Bs[nb][ahalf * 4 + 3][arow] = rb.w;
            __syncthreads();
            buf = nb;
        }
    }

    float bv[8];
#pragma unroll
    for (int j = 0; j < 4; j++) {
        bv[j]     = bias ? bias[n0 + tx * 4 + j]      : 0.f;
        bv[4 + j] = bias ? bias[n0 + 64 + tx * 4 + j] : 0.f;
    }
#pragma unroll
    for (int i = 0; i < 8; i++) {
        int m = m0 + ((i < 4) ? (ty * 4 + i) : (64 + ty * 4 + (i - 4)));
        float2 p0 = unpack2(acc2[i][0]), p1 = unpack2(acc2[i][1]);
        float2 p2 = unpack2(acc2[i][2]), p3 = unpack2(acc2[i][3]);
        float4 o0, o1;
        o0.x = p0.x + bv[0]; o0.y = p0.y + bv[1]; o0.z = p1.x + bv[2]; o0.w = p1.y + bv[3];
        o1.x = p2.x + bv[4]; o1.y = p2.y + bv[5]; o1.z = p3.x + bv[6]; o1.w = p3.y + bv[7];
        if (relu) {
            o0.x = fmaxf(o0.x, 0.f); o0.y = fmaxf(o0.y, 0.f);
            o0.z = fmaxf(o0.z, 0.f); o0.w = fmaxf(o0.w, 0.f);
            o1.x = fmaxf(o1.x, 0.f); o1.y = fmaxf(o1.y, 0.f);
            o1.z = fmaxf(o1.z, 0.f); o1.w = fmaxf(o1.w, 0.f);
        }
        *(float4*)&C[(size_t)m * Nout + n0 + tx * 4] = o0;
        *(float4*)&C[(size_t)m * Nout + n0 + 64 + tx * 4] = o1;
    }
}

// ---------------- GEMM(128x128) + residual + LayerNorm fused ----------------
__global__ void __launch_bounds__(256, 2)
gemm_ln128(const float* __restrict__ A, const float* __restrict__ W,
           const float* __restrict__ bias, float* __restrict__ hio,
           const float* __restrict__ gamma, const float* __restrict__ beta, int K) {
    __shared__ float As[2][8][128];
    __shared__ float Bs[2][8][128];
    const int tid = threadIdx.x;
    const int tx = tid & 15, ty = tid >> 4;
    const int m0 = blockIdx.y * 128;
    unsigned long long acc2[8][4];
#pragma unroll
    for (int i = 0; i < 8; i++)
#pragma unroll
        for (int j = 0; j < 4; j++) acc2[i][j] = 0ull;

    const int arow = tid >> 1, ahalf = tid & 1;
    const float* Aptr = A + (size_t)(m0 + arow) * K + ahalf * 4;
    const float* Wptr = W + (size_t)arow * K + ahalf * 4;

    const int KC = K >> 3;
    float4 ra = *(const float4*)(Aptr);
    float4 rb = *(const float4*)(Wptr);
    As[0][ahalf * 4 + 0][arow] = ra.x; As[0][ahalf * 4 + 1][arow] = ra.y;
    As[0][ahalf * 4 + 2][arow] = ra.z; As[0][ahalf * 4 + 3][arow] = ra.w;
    Bs[0][ahalf * 4 + 0][arow] = rb.x; Bs[0][ahalf * 4 + 1][arow] = rb.y;
    Bs[0][ahalf * 4 + 2][arow] = rb.z; Bs[0][ahalf * 4 + 3][arow] = rb.w;
    __syncthreads();

    int buf = 0;
    for (int kc = 0; kc < KC; kc++) {
        if (kc + 1 < KC) {
            ra = *(const float4*)(Aptr + (kc + 1) * 8);
            rb = *(const float4*)(Wptr + (kc + 1) * 8);
        }
#pragma unroll
        for (int k = 0; k < 8; k++) {
            ulonglong2 q0 = *(const ulonglong2*)&Bs[buf][k][tx * 4];
            ulonglong2 q1 = *(const ulonglong2*)&Bs[buf][k][64 + tx * 4];
            unsigned long long bp[4] = {q0.x, q0.y, q1.x, q1.y};
            float4 a0 = *(const float4*)&As[buf][k][ty * 4];
            float4 a1 = *(const float4*)&As[buf][k][64 + ty * 4];
            float aa[8] = {a0.x, a0.y, a0.z, a0.w, a1.x, a1.y, a1.z, a1.w};
#pragma unroll
            for (int i = 0; i < 8; i++) {
                unsigned long long ad = pack2(aa[i], aa[i]);
#pragma unroll
                for (int j = 0; j < 4; j++) ffma2(acc2[i][j], ad, bp[j]);
            }
        }
        if (kc + 1 < KC) {
            int nb = buf ^ 1;
            As[nb][ahalf * 4 + 0][arow] = ra.x; As[nb][ahalf * 4 + 1][arow] = ra.y;
            As[nb][ahalf * 4 + 2][arow] = ra.z; As[nb][ahalf * 4 + 3][arow] = ra.w;
            Bs[nb][ahalf * 4 + 0][arow] = rb.x; Bs[nb][ahalf * 4 + 1][arow] = rb.y;
            Bs[nb][ahalf * 4 + 2][arow] = rb.z; Bs[nb][ahalf * 4 + 3][arow] = rb.w;
            __syncthreads();
            buf = nb;
        }
    }

#pragma unroll
    for (int i = 0; i < 8; i++) {
        int m = m0 + ((i < 4) ? (ty * 4 + i) : (64 + ty * 4 + (i - 4)));
        float2 p0 = unpack2(acc2[i][0]), p1 = unpack2(acc2[i][1]);
        float2 p2 = unpack2(acc2[i][2]), p3 = unpack2(acc2[i][3]);
        float4 h0 = *(const float4*)&hio[(size_t)m * 128 + tx * 4];
        float4 h1 = *(const float4*)&hio[(size_t)m * 128 + 64 + tx * 4];
        float x[8];
        x[0] = p0.x + bias[tx * 4 + 0] + h0.x;
        x[1] = p0.y + bias[tx * 4 + 1] + h0.y;
        x[2] = p1.x + bias[tx * 4 + 2] + h0.z;
        x[3] = p1.y + bias[tx * 4 + 3] + h0.w;
        x[4] = p2.x + bias[64 + tx * 4 + 0] + h1.x;
        x[5] = p2.y + bias[64 + tx * 4 + 1] + h1.y;
        x[6] = p3.x + bias[64 + tx * 4 + 2] + h1.z;
        x[7] = p3.y + bias[64 + tx * 4 + 3] + h1.w;
        float s = 0.f;
#pragma unroll
        for (int j = 0; j < 8; j++) s += x[j];
#pragma unroll
        for (int off = 1; off < 16; off <<= 1)
            s += __shfl_xor_sync(0xffffffffu, s, off);
        float mean = s * 0.0078125f;
        float c[8], v = 0.f;
#pragma unroll
        for (int j = 0; j < 8; j++) { c[j] = x[j] - mean; v += c[j] * c[j]; }
#pragma unroll
        for (int off = 1; off < 16; off <<= 1)
            v += __shfl_xor_sync(0xffffffffu, v, off);
        float den = sqrtf(v * 0.0078125f + 1e-5f);
        float4 o0, o1;
        o0.x = c[0] / den * gamma[tx * 4 + 0] + beta[tx * 4 + 0];
        o0.y = c[1] / den * gamma[tx * 4 + 1] + beta[tx * 4 + 1];
        o0.z = c[2] / den * gamma[tx * 4 + 2] + beta[tx * 4 + 2];
        o0.w = c[3] / den * gamma[tx * 4 + 3] + beta[tx * 4 + 3];
        o1.x = c[4] / den * gamma[64 + tx * 4 + 0] + beta[64 + tx * 4 + 0];
        o1.y = c[5] / den * gamma[64 + tx * 4 + 1] + beta[64 + tx * 4 + 1];
        o1.z = c[6] / den * gamma[64 + tx * 4 + 2] + beta[64 + tx * 4 + 2];
        o1.w = c[7] / den * gamma[64 + tx * 4 + 3] + beta[64 + tx * 4 + 3];
        *(float4*)&hio[(size_t)m * 128 + tx * 4] = o0;
        *(float4*)&hio[(size_t)m * 128 + 64 + tx * 4] = o1;
    }
}

// ---------------- SGEMM 64x128, occ-3 (small GEMMs) ----------------
__global__ void __launch_bounds__(256, 3)
gemm64(const float* __restrict__ A, const float* __restrict__ W,
       const float* __restrict__ bias, float* __restrict__ C,
       int Nout, int K, int ldw, int relu) {
    __shared__ float As[2][8][64];
    __shared__ float Bs[2][8][128];
    const int tid = threadIdx.x;
    const int tx = tid & 15, ty = tid >> 4;
    const int m0 = blockIdx.y * 64, n0 = blockIdx.x * 128;
    unsigned long long acc2[4][4];
#pragma unroll
    for (int i = 0; i < 4; i++)
#pragma unroll
        for (int j = 0; j < 4; j++) acc2[i][j] = 0ull;

    const int arow = tid >> 1, ahalf = tid & 1;
    const bool aload = tid < 128;
    const float* Aptr = A + (size_t)(m0 + (aload ? arow : 0)) * K + ahalf * 4;
    const float* Wptr = W + (size_t)(n0 + arow) * ldw + ahalf * 4;

    const int KC = K >> 3;
    float4 ra = make_float4(0.f, 0.f, 0.f, 0.f), rb;
    if (aload) ra = *(const float4*)(Aptr);
    rb = *(const float4*)(Wptr);
    if (aload) {
        As[0][ahalf * 4 + 0][arow] = ra.x; As[0][ahalf * 4 + 1][arow] = ra.y;
        As[0][ahalf * 4 + 2][arow] = ra.z; As[0][ahalf * 4 + 3][arow] = ra.w;
    }
    Bs[0][ahalf * 4 + 0][arow] = rb.x; Bs[0][ahalf * 4 + 1][arow] = rb.y;
    Bs[0][ahalf * 4 + 2][arow] = rb.z; Bs[0][ahalf * 4 + 3][arow] = rb.w;
    __syncthreads();

    int buf = 0;
    for (int kc = 0; kc < KC; kc++) {
        if (kc + 1 < KC) {
            if (aload) ra = *(const float4*)(Aptr + (kc + 1) * 8);
            rb = *(const float4*)(Wptr + (kc + 1) * 8);
        }
#pragma unroll
        for (int k = 0; k < 8; k++) {
            ulonglong2 q0 = *(const ulonglong2*)&Bs[buf][k][tx * 4];
            ulonglong2 q1 = *(const ulonglong2*)&Bs[buf][k][64 + tx * 4];
            unsigned long long bp[4] = {q0.x, q0.y, q1.x, q1.y};
            float4 a0 = *(const float4*)&As[buf][k][ty * 4];
            float aa[4] = {a0.x, a0.y, a0.z, a0.w};
#pragma unroll
            for (int i = 0; i < 4; i++) {
                unsigned long long ad = pack2(aa[i], aa[i]);
#pragma unroll
                for (int j = 0; j < 4; j++) ffma2(acc2[i][j], ad, bp[j]);
            }
        }
        if (kc + 1 < KC) {
            int nb = buf ^ 1;
            if (aload) {
                As[nb][ahalf * 4 + 0][arow] = ra.x; As[nb][ahalf * 4 + 1][arow] = ra.y;
                As[nb][ahalf * 4 + 2][arow] = ra.z; As[nb][ahalf * 4 + 3][arow] = ra.w;
            }
            Bs[nb][ahalf * 4 + 0][arow] = rb.x; Bs[nb][ahalf * 4 + 1][arow] = rb.y;
            Bs[nb][ahalf * 4 + 2][arow] = rb.z; Bs[nb][ahalf * 4 + 3][arow] = rb.w;
            __syncthreads();
            buf = nb;
        }
    }

    float bv[8];
#pragma unroll
    for (int j = 0; j < 4; j++) {
        bv[j]     = bias ? bias[n0 + tx * 4 + j]      : 0.f;
        bv[4 + j] = bias ? bias[n0 + 64 + tx * 4 + j] : 0.f;
    }
#pragma unroll
    for (int i = 0; i < 4; i++) {
        int m = m0 + ty * 4 + i;
        float2 p0 = unpack2(acc2[i][0]), p1 = unpack2(acc2[i][1]);
        float2 p2 = unpack2(acc2[i][2]), p3 = unpack2(acc2[i][3]);
        float4 o0, o1;
        o0.x = p0.x + bv[0]; o0.y = p0.y + bv[1]; o0.z = p1.x + bv[2]; o0.w = p1.y + bv[3];
        o1.x = p2.x + bv[4]; o1.y = p2.y + bv[5]; o1.z = p3.x + bv[6]; o1.w = p3.y + bv[7];
        if (relu) {
            o0.x = fmaxf(o0.x, 0.f); o0.y = fmaxf(o0.y, 0.f);
            o0.z = fmaxf(o0.z, 0.f); o0.w = fmaxf(o0.w, 0.f);
            o1.x = fmaxf(o1.x, 0.f); o1.y = fmaxf(o1.y, 0.f);
            o1.z = fmaxf(o1.z, 0.f); o1.w = fmaxf(o1.w, 0.f);
        }
        *(float4*)&C[(size_t)m * Nout + n0 + tx * 4] = o0;
        *(float4*)&C[(size_t)m * Nout + n0 + 64 + tx * 4] = o1;
    }
}

// ---------------- batched bounded GEMM (S1) ----------------
__global__ void __launch_bounds__(256, 3)
gemm_batched(const float* __restrict__ A0, const float* __restrict__ W0,
             float* __restrict__ C0, int M, int Nout, int K,
             long long sA, long long sW, long long sC) {
    __shared__ float As[2][8][64];
    __shared__ float Bs[2][8][128];
    const float* A = A0 + (long long)blockIdx.z * sA;
    const float* W = W0 + (long long)blockIdx.z * sW;
    float* C = C0 + (long long)blockIdx.z * sC;
    const int tid = threadIdx.x;
    const int tx = tid & 15, ty = tid >> 4;
    const int m0 = blockIdx.y * 64, n0 = blockIdx.x * 128;
    unsigned long long acc2[4][4];
#pragma unroll
    for (int i = 0; i < 4; i++)
#pragma unroll
        for (int j = 0; j < 4; j++) acc2[i][j] = 0ull;

    const int arow = tid >> 1, ahalf = tid & 1;
    const bool aload = tid < 128;
    const bool aok = aload && (m0 + arow < M);
    const bool wok = (n0 + arow < Nout);
    const float* Aptr = A + (size_t)(aok ? (m0 + arow) : 0) * K + ahalf * 4;
    const float* Wptr = W + (size_t)(wok ? (n0 + arow) : 0) * K + ahalf * 4;

    const int KC = K >> 3;
    float4 ra = make_float4(0.f, 0.f, 0.f, 0.f), rb;
    if (aload) ra = *(const float4*)(Aptr);
    rb = *(const float4*)(Wptr);
    if (aload) {
        As[0][ahalf * 4 + 0][arow] = ra.x; As[0][ahalf * 4 + 1][arow] = ra.y;
        As[0][ahalf * 4 + 2][arow] = ra.z; As[0][ahalf * 4 + 3][arow] = ra.w;
    }
    Bs[0][ahalf * 4 + 0][arow] = rb.x; Bs[0][ahalf * 4 + 1][arow] = rb.y;
    Bs[0][ahalf * 4 + 2][arow] = rb.z; Bs[0][ahalf * 4 + 3][arow] = rb.w;
    __syncthreads();

    int buf = 0;
    for (int kc = 0; kc < KC; kc++) {
        if (kc + 1 < KC) {
            if (aload) ra = *(const float4*)(Aptr + (kc + 1) * 8);
            rb = *(const float4*)(Wptr + (kc + 1) * 8);
        }
#pragma unroll
        for (int k = 0; k < 8; k++) {
            ulonglong2 q0 = *(const ulonglong2*)&Bs[buf][k][tx * 4];
            ulonglong2 q1 = *(const ulonglong2*)&Bs[buf][k][64 + tx * 4];
            unsigned long long bp[4] = {q0.x, q0.y, q1.x, q1.y};
            float4 a0 = *(const float4*)&As[buf][k][ty * 4];
            float aa[4] = {a0.x, a0.y, a0.z, a0.w};
#pragma unroll
            for (int i = 0; i < 4; i++) {
                unsigned long long ad = pack2(aa[i], aa[i]);
#pragma unroll
                for (int j = 0; j < 4; j++) ffma2(acc2[i][j], ad, bp[j]);
            }
        }
        if (kc + 1 < KC) {
            int nb = buf ^ 1;
            if (aload) {
                As[nb][ahalf * 4 + 0][arow] = ra.x; As[nb][ahalf * 4 + 1][arow] = ra.y;
                As[nb][ahalf * 4 + 2][arow] = ra.z; As[nb][ahalf * 4 + 3][arow] = ra.w;
            }
            Bs[nb][ahalf * 4 + 0][arow] = rb.x; Bs[nb][ahalf * 4 + 1][arow] = rb.y;
            Bs[nb][ahalf * 4 + 2][arow] = rb.z; Bs[nb][ahalf * 4 + 3][arow] = rb.w;
            __syncthreads();
            buf = nb;
        }
    }

#pragma unroll
    for (int i = 0; i < 4; i++) {
        int m = m0 + ty * 4 + i;
        if (m >= M) continue;
        float2 p0 = unpack2(acc2[i][0]), p1 = unpack2(acc2[i][1]);
        float2 p2 = unpack2(acc2[i][2]), p3 = unpack2(acc2[i][3]);
        int c0 = n0 + tx * 4, c1 = n0 + 64 + tx * 4;
        if (c0 + 3 < Nout) {
            float4 o; o.x = p0.x; o.y = p0.y; o.z = p1.x; o.w = p1.y;
            *(float4*)&C[(size_t)m * Nout + c0] = o;
        }
        if (c1 + 3 < Nout) {
            float4 o; o.x = p2.x; o.y = p2.y; o.z = p3.x; o.w = p3.y;
            *(float4*)&C[(size_t)m * Nout + c1] = o;
        }
    }
}

// ---------------- attention ----------------
__global__ void __launch_bounds__(256)
attention_smem(const float* __restrict__ qkv, float* __restrict__ out) {
    int bh = blockIdx.x;
    int b = bh >> 3, h = bh & 7;
    __shared__ float QsT[DH_][208], KsT[DH_][208], VsT[DH_][208];
    const float* base = qkv + (size_t)b * N_ * 384 + h * DH_;
    int tid = threadIdx.x;
    for (int i = tid; i < N_ * DH_; i += 256) {
        int n = i >> 4, d = i & 15;
        const float* rp = base + (size_t)n * 384 + d;
        QsT[d][n] = rp[0];
        KsT[d][n] = rp[128];
        VsT[d][n] = rp[256];
    }
    __syncthreads();
    int warp = tid >> 5, lane = tid & 31;
    for (int q = warp; q < N_; q += 8) {
        float qv[DH_];
#pragma unroll
        for (int d = 0; d < DH_; d++) qv[d] = QsT[d][q];
        float s[7];
        float mx = -INFINITY;
#pragma unroll
        for (int j = 0; j < 7; j++) {
            int k = lane + 32 * j;
            float a = 0.f;
            if (k < N_) {
#pragma unroll
                for (int d = 0; d < DH_; d++) a += qv[d] * KsT[d][k];
                a *= 0.25f;
            } else a = -INFINITY;
            s[j] = a;
            mx = fmaxf(mx, a);
        }
#pragma unroll
        for (int off = 16; off; off >>= 1)
            mx = fmaxf(mx, __shfl_xor_sync(0xffffffffu, mx, off));
        float p[7];
        float sum = 0.f;
#pragma unroll
        for (int j = 0; j < 7; j++) {
            int k = lane + 32 * j;
            p[j] = (k < N_) ? expf(s[j] - mx) : 0.f;
            sum += p[j];
        }
#pragma unroll
        for (int off = 16; off; off >>= 1)
            sum += __shfl_xor_sync(0xffffffffu, sum, off);
        float inv = 1.f / sum;
        float o[DH_];
#pragma unroll
        for (int d = 0; d < DH_; d++) o[d] = 0.f;
#pragma unroll
        for (int j = 0; j < 7; j++) {
            int k = lane + 32 * j;
            if (k < N_) {
                float wgt = p[j] * inv;
#pragma unroll
                for (int d = 0; d < DH_; d++) o[d] += wgt * VsT[d][k];
            }
        }
#pragma unroll
        for (int d = 0; d < DH_; d++) {
            float v = o[d];
#pragma unroll
            for (int off = 16; off; off >>= 1)
                v += __shfl_xor_sync(0xffffffffu, v, off);
            if (lane == d)
                out[((size_t)b * N_ + q) * D_ + h * DH_ + d] = v;
        }
    }
}

// ---------------- small precompute kernels ----------------
__global__ void compute_M_kernel(const float* __restrict__ Wq, const float* __restrict__ Wctx) {
    int d = blockIdx.y;
    int c = blockIdx.x * blockDim.x + threadIdx.x;
    if (c >= 3 * D_) return;
    float acc = 0.f;
    for (int k = 0; k < D_; k++) acc += Wq[d * D_ + k] * Wctx[k * (3 * D_) + c];
    g_M[d * (3 * D_) + c] = acc;
}

__global__ void compute_vecs_kernel(const float* __restrict__ Wq, const float* __restrict__ bctx,
                                    const float* __restrict__ Wcap, const float* __restrict__ bcap) {
    int d = threadIdx.x;
    float a = 0.f, u = 0.f, bq = 0.f;
    for (int k = 0; k < D_; k++) {
        float m = g_M[d * (3 * D_) + 2 * D_ + k];
        a += m * bcap[k];
        u += m * Wcap[k];
        bq += Wq[d * D_ + k] * bctx[k];
    }
    g_vconst[d] = a + bq;
    g_vu[d] = u;
}

__global__ void compute_gctx_kernel() {
    int b = blockIdx.x, d = threadIdx.x;
    float s = 0.f;
    for (int n = 0; n < N_; n++) s += g_h[((size_t)b * N_ + n) * D_ + d];
    g_gctx[b * D_ + d] = s / (float)N_;
}

__global__ void compute_qctx_kernel() {
    int b = blockIdx.x, d = threadIdx.x;
    float a = g_vconst[d];
    for (int k = 0; k < D_; k++) a += g_M[d * (3 * D_) + D_ + k] * g_gctx[b * D_ + k];
    g_qctx[b * D_ + d] = a;
}

__global__ void compute_CU_kernel() {
    int i = blockIdx.x * blockDim.x + threadIdx.x;
    if (i >= ROWS) return;
    int b = i / N_;
    const float* kr = g_kmat + (size_t)i * D_;
    float c = 0.f, u = 0.f;
    for (int d = 0; d < D_; d++) {
        c += kr[d] * g_qctx[b * D_ + d];
        u += kr[d] * g_vu[d];
    }
    g_C[i] = c;
    g_U[i] = u;
}

// ---------------- decode: 256-thread block, INLINE gumbel (feasible nodes only) ------------
__global__ void __launch_bounds__(256)
decode_kernel(float* __restrict__ path_out, float* __restrict__ lp_out) {
    int b = blockIdx.x;
    int t = threadIdx.x;
    int w = t >> 5, lane = t & 31;
    __shared__ unsigned char s_vis[256];
    __shared__ float s_masked[256];
    __shared__ unsigned s_bf[8], s_bu[8];
    __shared__ float s_wmax[8], s_wkey[8], s_wsum[8];
    __shared__ int s_widx[8];
    __shared__ float s_rem, s_acc;
    __shared__ int s_cur, s_done, s_cnt;

    s_vis[t] = 0;
    if (t == 0) {
        s_rem = 1.0f; s_cur = 0; s_done = 0; s_cnt = N_ - 1; s_acc = 0.f;
        path_out[(size_t)b * (STEPS + 1)] = 0.0f;
    }
    float drv = 0.f, Cv = 0.f, Uv = 0.f, s1v = 0.f;
    if (t < N_) {
        drv = g_dr[b * N_ + t];
        Cv = g_C[b * N_ + t];
        Uv = g_U[b * N_ + t];
        s1v = g_S1[(size_t)(b * N_ + 0) * N_ + t];
    }
    __syncthreads();

    for (int step = 0; step < STEPS; step++) {
        float rem = s_rem;
        int cur = s_cur;
        int done = s_done;
        bool vis = s_vis[t] != 0;

        bool feas = (t >= 1 && t < N_) && !vis && (drv <= rem);
        bool unv = (t >= 1 && t < N_) && !vis;
        unsigned bfm = __ballot_sync(0xffffffffu, feas);
        unsigned bum = __ballot_sync(0xffffffffu, unv);
        if (lane == 0) { s_bf[w] = bfm; s_bu[w] = bum; }
        __syncthreads();
        unsigned fb = 0, ub = 0;
#pragma unroll
        for (int i = 0; i < 8; i++) { fb |= s_bf[i]; ub |= s_bu[i]; }
        bool has_feas = fb != 0, all_served = (ub == 0);

        bool at_depot = (cur == 0) && !done;
        bool not_depot = (cur != 0) && !done;
        bool depot_mask = (at_depot && has_feas) ||
                          (not_depot && has_feas && !all_served);
        bool force_depot = (all_served && (cur != 0) && !done) ||
                           (not_depot && !has_feas) || done;

        float m = -INFINITY, keyv = -INFINITY;
        if (t < N_) {
            bool infeas = vis || (drv > rem);
            if (t == 0) infeas = infeas || depot_mask;
            float logit = (s1v + Cv + rem * Uv) / SQRTD;
            m = infeas ? -1e9f : logit;
            s_masked[t] = m;
            keyv = m;  // infeasible: -1e9+gum rounds to -1e9 exactly (|gum|<32=ulp/2)
            if (!infeas) {
                uint2 y = threefry2x32(c_keys.x[step], c_keys.y[step],
                                       0u, (uint32_t)(b * N_ + t));
                uint32_t bits = y.x ^ y.y;
                float f = __uint_as_float((bits >> 9) | 0x3f800000u) - 1.0f;
                float u = (f == 0.f) ? 1.17549435e-38f : f;
                keyv = m - logf(-logf(u));
            }
        }
        // single warp pass: max(m), argmax(keyv), sum(exp(m - warpmax))
        float mxm = m, kv = keyv;
        int ki = t;
#pragma unroll
        for (int off = 16; off; off >>= 1) {
            mxm = fmaxf(mxm, __shfl_xor_sync(0xffffffffu, mxm, off));
            float kv2 = __shfl_xor_sync(0xffffffffu, kv, off);
            int ki2 = __shfl_xor_sync(0xffffffffu, ki, off);
            if (kv2 > kv || (kv2 == kv && ki2 < ki)) { kv = kv2; ki = ki2; }
        }
        float e = (t < N_) ? expf(m - mxm) : 0.f;
#pragma unroll
        for (int off = 16; off; off >>= 1)
            e += __shfl_xor_sync(0xffffffffu, e, off);
        if (lane == 0) { s_wmax[w] = mxm; s_wkey[w] = kv; s_widx[w] = ki; s_wsum[w] = e; }
        __syncthreads();
        float mx = s_wmax[0], bk = s_wkey[0];
        int bi = s_widx[0];
#pragma unroll
        for (int i = 1; i < 8; i++) {
            mx = fmaxf(mx, s_wmax[i]);
            float k2 = s_wkey[i];
            if (k2 > bk) { bk = k2; bi = s_widx[i]; }
        }
        int ncur = force_depot ? 0 : bi;
        // prefetch next step's S1 row while t0 finishes bookkeeping
        float s1n = 0.f;
        if (step + 1 < STEPS && t < N_)
            s1n = g_S1[(size_t)(b * N_ + ncur) * N_ + t];
        if (t == 0) {
            float sum = 0.f;
#pragma unroll
            for (int i = 0; i < 8; i++) sum += s_wsum[i] * expf(s_wmax[i] - mx);
            int sel = bi;
            float slp = s_masked[sel] - mx - logf(sum);
            if (force_depot) { sel = 0; slp = 0.f; }
            bool isd = (sel == 0);
            float take = g_dr[b * N_ + sel];
            float nr = isd ? 1.0f : (rem - take);
            nr = fminf(fmaxf(nr, 0.f), 1.f);
            s_rem = nr;
            if (!isd && !s_vis[sel]) { s_vis[sel] = 1; s_cnt--; }
            s_cur = sel;
            s_done = done || (s_cnt == 0 && isd);
            s_acc += slp;
            path_out[(size_t)b * (STEPS + 1) + 1 + step] = (float)sel;
        }
        __syncthreads();
        s1v = s1n;
    }
    if (t == 0 && lp_out) lp_out[b] = s_acc;
}

// ---------------- launch ----------------
extern "C" void kernel_launch(void* const* d_in, const int* in_sizes, int n_in,
                              void* d_out, int out_size) {
    int perm[23];
    for (int i = 0; i < 23; i++) perm[i] = i;
    if (n_in >= 23 && in_sizes[0] == 786432) {
        const int m[23] = {15,16,14,17,18,7,13,5,12,0,8,1,9,20,19,22,21,6,4,2,10,3,11};
        for (int i = 0; i < 23; i++) perm[i] = m[i];
    }
    const float* coords   = (const float*)d_in[perm[0]];
    const float* demands  = (const float*)d_in[perm[1]];
    const float* capacity = (const float*)d_in[perm[2]];
    const float* embed_W  = (const float*)d_in[perm[3]];
    const float* embed_b  = (const float*)d_in[perm[4]];
    const float* Wqkv     = (const float*)d_in[perm[5]];
    const float* bqkv     = (const float*)d_in[perm[6]];
    const float* Wo       = (const float*)d_in[perm[7]];
    const float* bo       = (const float*)d_in[perm[8]];
    const float* W1       = (const float*)d_in[perm[9]];
    const float* b1       = (const float*)d_in[perm[10]];
    const float* W2       = (const float*)d_in[perm[11]];
    const float* b2       = (const float*)d_in[perm[12]];
    const float* ln1_g    = (const float*)d_in[perm[13]];
    const float* ln1_b    = (const float*)d_in[perm[14]];
    const float* ln2_g    = (const float*)d_in[perm[15]];
    const float* ln2_b    = (const float*)d_in[perm[16]];
    const float* Wq       = (const float*)d_in[perm[17]];
    const float* Wk       = (const float*)d_in[perm[18]];
    const float* Wcap     = (const float*)d_in[perm[19]];
    const float* bcap     = (const float*)d_in[perm[20]];
    const float* Wctx     = (const float*)d_in[perm[21]];
    const float* bctx     = (const float*)d_in[perm[22]];

    float *g_h_p, *g_qkv_p, *g_att_p, *g_ffn_p, *g_kmat_p, *g_hM_p, *g_S1_p, *g_M_p;
    cudaGetSymbolAddress((void**)&g_h_p, g_h);
    cudaGetSymbolAddress((void**)&g_qkv_p, g_qkv);
    cudaGetSymbolAddress((void**)&g_att_p, g_att);
    cudaGetSymbolAddress((void**)&g_ffn_p, g_ffn);
    cudaGetSymbolAddress((void**)&g_kmat_p, g_kmat);
    cudaGetSymbolAddress((void**)&g_hM_p, g_hM);
    cudaGetSymbolAddress((void**)&g_S1_p, g_S1);
    cudaGetSymbolAddress((void**)&g_M_p, g_M);

    embed_kernel<<<ROWS, 128>>>(coords, demands, capacity, embed_W, embed_b);

    for (int i = 0; i < L_; i++) {
        gemm128<<<dim3(3, 200), 256>>>(
            g_h_p, Wqkv + (size_t)i * 384 * 128, bqkv + i * 384, g_qkv_p,
            384, 128, 128, 0);
        attention_smem<<<B_ * H_, 256>>>(g_qkv_p, g_att_p);
        gemm_ln128<<<dim3(1, 200), 256>>>(
            g_att_p, Wo + (size_t)i * 128 * 128, bo + i * 128, g_h_p,
            ln1_g + i * 128, ln1_b + i * 128, 128);
        gemm128<<<dim3(16, 200), 256>>>(
            g_h_p, W1 + (size_t)i * F_ * 128, b1 + i * F_, g_ffn_p,
            F_, 128, 128, 1);
        gemm_ln128<<<dim3(1, 200), 256>>>(
            g_ffn_p, W2 + (size_t)i * 128 * F_, b2 + i * 128, g_h_p,
            ln2_g + i * 128, ln2_b + i * 128, F_);
    }

    compute_gctx_kernel<<<B_, 128>>>();
    compute_M_kernel<<<dim3(3, 128), 128>>>(Wq, Wctx);
    compute_vecs_kernel<<<1, 128>>>(Wq, bctx, Wcap, bcap);
    compute_qctx_kernel<<<B_, 128>>>();
    gemm64<<<dim3(1, 400), 256>>>(g_h_p, Wk, nullptr, g_kmat_p, 128, 128, 128, 0);
    gemm64<<<dim3(1, 400), 256>>>(g_h_p, g_M_p, nullptr, g_hM_p, 128, 128, 384, 0);
    gemm_batched<<<dim3(2, 4, B_), 256>>>(
        g_hM_p, g_kmat_p, g_S1_p, N_, N_, 128,
        (long long)N_ * 128, (long long)N_ * 128, (long long)N_ * N_);
    compute_CU_kernel<<<(ROWS + 255) / 256, 256>>>();

    float* out_f = (float*)d_out;
    float* lp_out = (out_size >= B_ * (STEPS + 1) + B_) ? (out_f + B_ * (STEPS + 1)) : nullptr;
    decode_kernel<<<B_, 256>>>(out_f, lp_out);
}

// round 10
// speedup vs baseline: 1.1897x; 1.0894x over previous
#include <cuda_runtime.h>
#include <stdint.h>
#include <math.h>

// ---------------- problem constants ----------------
static constexpr int B_ = 128, N_ = 200, D_ = 128, H_ = 8, DH_ = 16, L_ = 3, F_ = 2048;
static constexpr int ROWS = B_ * N_;            // 25600
static constexpr int STEPS = 2 * (N_ - 1) + 1;  // 399
static constexpr float SQRTD = 11.313708498984761f;

// ---------------- scratch ----------------
__device__ float g_h[ROWS * D_];
__device__ float g_qkv[ROWS * 3 * D_];
__device__ float g_att[ROWS * D_];
__device__ float g_ffn[ROWS * F_];
__device__ float g_part[4 * ROWS * D_];   // split-K partials for FFN2
__device__ float g_kmat[ROWS * D_];
__device__ float g_hM[ROWS * D_];
__device__ float g_S1[B_ * N_ * N_];
__device__ float g_dr[ROWS];
__device__ float g_gctx[B_ * D_];
__device__ float g_M[D_ * 3 * D_];
__device__ float g_vconst[D_];
__device__ float g_vu[D_];
__device__ float g_qctx[B_ * D_];
__device__ float g_C[ROWS];
__device__ float g_U[ROWS];

// ---------------- compile-time threefry key chain (key(42) is constant) ----------------
struct U2c { uint32_t a, b; };
constexpr uint32_t crotl(uint32_t v, int d) { return (v << d) | (v >> (32 - d)); }
constexpr U2c ctf(uint32_t k0, uint32_t k1, uint32_t x0, uint32_t x1) {
    uint32_t ks2 = k0 ^ k1 ^ 0x1BD11BDAu;
    x0 += k0; x1 += k1;
    const int r0[4] = {13, 15, 26, 6};
    const int r1[4] = {17, 29, 16, 24};
    for (int i = 0; i < 4; i++) { x0 += x1; x1 = crotl(x1, r0[i]); x1 ^= x0; }
    x0 += k1; x1 += ks2 + 1u;
    for (int i = 0; i < 4; i++) { x0 += x1; x1 = crotl(x1, r1[i]); x1 ^= x0; }
    x0 += ks2; x1 += k0 + 2u;
    for (int i = 0; i < 4; i++) { x0 += x1; x1 = crotl(x1, r0[i]); x1 ^= x0; }
    x0 += k0; x1 += k1 + 3u;
    for (int i = 0; i < 4; i++) { x0 += x1; x1 = crotl(x1, r1[i]); x1 ^= x0; }
    x0 += k1; x1 += ks2 + 4u;
    for (int i = 0; i < 4; i++) { x0 += x1; x1 = crotl(x1, r0[i]); x1 ^= x0; }
    x0 += ks2; x1 += k0 + 5u;
    return {x0, x1};
}
struct KeysCT { uint32_t x[STEPS]; uint32_t y[STEPS]; };
constexpr KeysCT make_keys_ct() {
    KeysCT K{};
    uint32_t k0 = 0u, k1 = 42u;
    for (int t = 0; t < STEPS; t++) {
        U2c nk = ctf(k0, k1, 0u, 0u);
        U2c sk = ctf(k0, k1, 0u, 1u);
        K.x[t] = sk.a; K.y[t] = sk.b;
        k0 = nk.a; k1 = nk.b;
    }
    return K;
}
__constant__ KeysCT c_keys = make_keys_ct();

// ---------------- f32x2 helpers ----------------
__device__ __forceinline__ void ffma2(unsigned long long& d, unsigned long long a,
                                      unsigned long long b) {
    asm("fma.rn.f32x2 %0, %1, %2, %0;" : "+l"(d) : "l"(a), "l"(b));
}
__device__ __forceinline__ unsigned long long pack2(float lo, float hi) {
    unsigned long long r;
    asm("mov.b64 %0, {%1, %2};" : "=l"(r) : "f"(lo), "f"(hi));
    return r;
}
__device__ __forceinline__ float2 unpack2(unsigned long long v) {
    float2 r;
    asm("mov.b64 {%0, %1}, %2;" : "=f"(r.x), "=f"(r.y) : "l"(v));
    return r;
}

// ---------------- threefry2x32 runtime ----------------
__device__ __forceinline__ uint32_t rotl32(uint32_t x, int d) {
    return (x << d) | (x >> (32 - d));
}
__device__ __forceinline__ uint2 threefry2x32(uint32_t k0, uint32_t k1,
                                              uint32_t x0, uint32_t x1) {
    uint32_t ks2 = k0 ^ k1 ^ 0x1BD11BDAu;
    x0 += k0; x1 += k1;
    const int r0[4] = {13, 15, 26, 6};
    const int r1[4] = {17, 29, 16, 24};
#pragma unroll
    for (int i = 0; i < 4; i++) { x0 += x1; x1 = rotl32(x1, r0[i]); x1 ^= x0; }
    x0 += k1; x1 += ks2 + 1u;
#pragma unroll
    for (int i = 0; i < 4; i++) { x0 += x1; x1 = rotl32(x1, r1[i]); x1 ^= x0; }
    x0 += ks2; x1 += k0 + 2u;
#pragma unroll
    for (int i = 0; i < 4; i++) { x0 += x1; x1 = rotl32(x1, r0[i]); x1 ^= x0; }
    x0 += k0; x1 += k1 + 3u;
#pragma unroll
    for (int i = 0; i < 4; i++) { x0 += x1; x1 = rotl32(x1, r1[i]); x1 ^= x0; }
    x0 += k1; x1 += ks2 + 4u;
#pragma unroll
    for (int i = 0; i < 4; i++) { x0 += x1; x1 = rotl32(x1, r0[i]); x1 ^= x0; }
    x0 += ks2; x1 += k0 + 5u;
    return make_uint2(x0, x1);
}

// ---------------- embed ----------------
__global__ void embed_kernel(const float* __restrict__ coords,
                             const float* __restrict__ demands,
                             const float* __restrict__ cap,
                             const float* __restrict__ W,
                             const float* __restrict__ bias) {
    int row = blockIdx.x;
    int d = threadIdx.x;
    int b = row / N_;
    float cx = coords[row * 2 + 0];
    float cy = coords[row * 2 + 1];
    float r = demands[row] / cap[b];
    if (d == 0) g_dr[row] = r;
    float v = W[d * 3 + 0] * cx + W[d * 3 + 1] * cy + W[d * 3 + 2] * r + bias[d];
    g_h[(size_t)row * D_ + d] = v;
}

// ---------------- SGEMM 128x128 tile, occ-2 ----------------
__global__ void __launch_bounds__(256, 2)
gemm128(const float* __restrict__ A, const float* __restrict__ W,
        const float* __restrict__ bias, float* __restrict__ C,
        int Nout, int K, int ldw, int relu) {
    __shared__ float As[2][8][128];
    __shared__ float Bs[2][8][128];
    const int tid = threadIdx.x;
    const int tx = tid & 15, ty = tid >> 4;
    const int m0 = blockIdx.y * 128, n0 = blockIdx.x * 128;
    unsigned long long acc2[8][4];
#pragma unroll
    for (int i = 0; i < 8; i++)
#pragma unroll
        for (int j = 0; j < 4; j++) acc2[i][j] = 0ull;

    const int arow = tid >> 1, ahalf = tid & 1;
    const float* Aptr = A + (size_t)(m0 + arow) * K + ahalf * 4;
    const float* Wptr = W + (size_t)(n0 + arow) * ldw + ahalf * 4;

    const int KC = K >> 3;
    float4 ra = *(const float4*)(Aptr);
    float4 rb = *(const float4*)(Wptr);
    As[0][ahalf * 4 + 0][arow] = ra.x; As[0][ahalf * 4 + 1][arow] = ra.y;
    As[0][ahalf * 4 + 2][arow] = ra.z; As[0][ahalf * 4 + 3][arow] = ra.w;
    Bs[0][ahalf * 4 + 0][arow] = rb.x; Bs[0][ahalf * 4 + 1][arow] = rb.y;
    Bs[0][ahalf * 4 + 2][arow] = rb.z; Bs[0][ahalf * 4 + 3][arow] = rb.w;
    __syncthreads();

    int buf = 0;
    for (int kc = 0; kc < KC; kc++) {
        if (kc + 1 < KC) {
            ra = *(const float4*)(Aptr + (kc + 1) * 8);
            rb = *(const float4*)(Wptr + (kc + 1) * 8);
        }
#pragma unroll
        for (int k = 0; k < 8; k++) {
            ulonglong2 q0 = *(const ulonglong2*)&Bs[buf][k][tx * 4];
            ulonglong2 q1 = *(const ulonglong2*)&Bs[buf][k][64 + tx * 4];
            unsigned long long bp[4] = {q0.x, q0.y, q1.x, q1.y};
            float4 a0 = *(const float4*)&As[buf][k][ty * 4];
            float4 a1 = *(const float4*)&As[buf][k][64 + ty * 4];
            float aa[8] = {a0.x, a0.y, a0.z, a0.w, a1.x, a1.y, a1.z, a1.w};
#pragma unroll
            for (int i = 0; i < 8; i++) {
                unsigned long long ad = pack2(aa[i], aa[i]);
#pragma unroll
                for (int j = 0; j < 4; j++) ffma2(acc2[i][j], ad, bp[j]);
            }
        }
        if (kc + 1 < KC) {
            int nb = buf ^ 1;
            As[nb][ahalf * 4 + 0][arow] = ra.x; As[nb][ahalf * 4 + 1][arow] = ra.y;
            As[nb][ahalf * 4 + 2][arow] = ra.z; As[nb][ahalf * 4 + 3][arow] = ra.w;
            Bs[nb][ahalf * 4 + 0][arow] = rb.x; Bs[nb][ahalf * 4 + 1][arow] = rb.y;
            Bs[nb][ahalf * 4 + 2][arow] = rb.z; Bs[nb][ahalf * 4 + 3][arow] = rb.w;
            __syncthreads();
            buf = nb;
        }
    }

    float bv[8];
#pragma unroll
    for (int j = 0; j < 4; j++) {
        bv[j]     = bias ? bias[n0 + tx * 4 + j]      : 0.f;
        bv[4 + j] = bias ? bias[n0 + 64 + tx * 4 + j] : 0.f;
    }
#pragma unroll
    for (int i = 0; i < 8; i++) {
        int m = m0 + ((i < 4) ? (ty * 4 + i) : (64 + ty * 4 + (i - 4)));
        float2 p0 = unpack2(acc2[i][0]), p1 = unpack2(acc2[i][1]);
        float2 p2 = unpack2(acc2[i][2]), p3 = unpack2(acc2[i][3]);
        float4 o0, o1;
        o0.x = p0.x + bv[0]; o0.y = p0.y + bv[1]; o0.z = p1.x + bv[2]; o0.w = p1.y + bv[3];
        o1.x = p2.x + bv[4]; o1.y = p2.y + bv[5]; o1.z = p3.x + bv[6]; o1.w = p3.y + bv[7];
        if (relu) {
            o0.x = fmaxf(o0.x, 0.f); o0.y = fmaxf(o0.y, 0.f);
            o0.z = fmaxf(o0.z, 0.f); o0.w = fmaxf(o0.w, 0.f);
            o1.x = fmaxf(o1.x, 0.f); o1.y = fmaxf(o1.y, 0.f);
            o1.z = fmaxf(o1.z, 0.f); o1.w = fmaxf(o1.w, 0.f);
        }
        *(float4*)&C[(size_t)m * Nout + n0 + tx * 4] = o0;
        *(float4*)&C[(size_t)m * Nout + n0 + 64 + tx * 4] = o1;
    }
}

// ---------------- split-K GEMM: partial C_z = A[:, zK:(z+1)K] @ W[:, zK:(z+1)K]^T --------
// Nout fixed 128. C partial buffers: C + z*ROWS*128.
__global__ void __launch_bounds__(256, 2)
gemm_sk128(const float* __restrict__ A, const float* __restrict__ W,
           float* __restrict__ C, int Kslice, int lda, int ldw) {
    __shared__ float As[2][8][128];
    __shared__ float Bs[2][8][128];
    const int z = blockIdx.z;
    A += (size_t)z * Kslice;
    W += (size_t)z * Kslice;
    C += (size_t)z * ROWS * 128;
    const int tid = threadIdx.x;
    const int tx = tid & 15, ty = tid >> 4;
    const int m0 = blockIdx.y * 128;
    unsigned long long acc2[8][4];
#pragma unroll
    for (int i = 0; i < 8; i++)
#pragma unroll
        for (int j = 0; j < 4; j++) acc2[i][j] = 0ull;

    const int arow = tid >> 1, ahalf = tid & 1;
    const float* Aptr = A + (size_t)(m0 + arow) * lda + ahalf * 4;
    const float* Wptr = W + (size_t)arow * ldw + ahalf * 4;

    const int KC = Kslice >> 3;
    float4 ra = *(const float4*)(Aptr);
    float4 rb = *(const float4*)(Wptr);
    As[0][ahalf * 4 + 0][arow] = ra.x; As[0][ahalf * 4 + 1][arow] = ra.y;
    As[0][ahalf * 4 + 2][arow] = ra.z; As[0][ahalf * 4 + 3][arow] = ra.w;
    Bs[0][ahalf * 4 + 0][arow] = rb.x; Bs[0][ahalf * 4 + 1][arow] = rb.y;
    Bs[0][ahalf * 4 + 2][arow] = rb.z; Bs[0][ahalf * 4 + 3][arow] = rb.w;
    __syncthreads();

    int buf = 0;
    for (int kc = 0; kc < KC; kc++) {
        if (kc + 1 < KC) {
            ra = *(const float4*)(Aptr + (kc + 1) * 8);
            rb = *(const float4*)(Wptr + (kc + 1) * 8);
        }
#pragma unroll
        for (int k = 0; k < 8; k++) {
            ulonglong2 q0 = *(const ulonglong2*)&Bs[buf][k][tx * 4];
            ulonglong2 q1 = *(const ulonglong2*)&Bs[buf][k][64 + tx * 4];
            unsigned long long bp[4] = {q0.x, q0.y, q1.x, q1.y};
            float4 a0 = *(const float4*)&As[buf][k][ty * 4];
            float4 a1 = *(const float4*)&As[buf][k][64 + ty * 4];
            float aa[8] = {a0.x, a0.y, a0.z, a0.w, a1.x, a1.y, a1.z, a1.w};
#pragma unroll
            for (int i = 0; i < 8; i++) {
                unsigned long long ad = pack2(aa[i], aa[i]);
#pragma unroll
                for (int j = 0; j < 4; j++) ffma2(acc2[i][j], ad, bp[j]);
            }
        }
        if (kc + 1 < KC) {
            int nb = buf ^ 1;
            As[nb][ahalf * 4 + 0][arow] = ra.x; As[nb][ahalf * 4 + 1][arow] = ra.y;
            As[nb][ahalf * 4 + 2][arow] = ra.z; As[nb][ahalf * 4 + 3][arow] = ra.w;
            Bs[nb][ahalf * 4 + 0][arow] = rb.x; Bs[nb][ahalf * 4 + 1][arow] = rb.y;
            Bs[nb][ahalf * 4 + 2][arow] = rb.z; Bs[nb][ahalf * 4 + 3][arow] = rb.w;
            __syncthreads();
            buf = nb;
        }
    }

#pragma unroll
    for (int i = 0; i < 8; i++) {
        int m = m0 + ((i < 4) ? (ty * 4 + i) : (64 + ty * 4 + (i - 4)));
        float2 p0 = unpack2(acc2[i][0]), p1 = unpack2(acc2[i][1]);
        float2 p2 = unpack2(acc2[i][2]), p3 = unpack2(acc2[i][3]);
        float4 o0, o1;
        o0.x = p0.x; o0.y = p0.y; o0.z = p1.x; o0.w = p1.y;
        o1.x = p2.x; o1.y = p2.y; o1.z = p3.x; o1.w = p3.y;
        *(float4*)&C[(size_t)m * 128 + tx * 4] = o0;
        *(float4*)&C[(size_t)m * 128 + 64 + tx * 4] = o1;
    }
}

// ---------------- join 4 partials + bias + residual + LN: h = LN(h + sum + b) -----------
__global__ void ln_join4(float* __restrict__ h, const float* __restrict__ bias,
                         const float* __restrict__ gamma, const float* __restrict__ beta) {
    int row = blockIdx.x;
    int d = threadIdx.x;
    __shared__ float sm[128];
    size_t idx = (size_t)row * 128 + d;
    float s = g_part[idx] + g_part[(size_t)ROWS * 128 + idx];
    s += g_part[(size_t)2 * ROWS * 128 + idx];
    s += g_part[(size_t)3 * ROWS * 128 + idx];
    float x = h[idx] + s + bias[d];
    sm[d] = x;
    __syncthreads();
    for (int st = 64; st > 0; st >>= 1) {
        if (d < st) sm[d] += sm[d + st];
        __syncthreads();
    }
    float mean = sm[0] / 128.f;
    __syncthreads();
    float c = x - mean;
    sm[d] = c * c;
    __syncthreads();
    for (int st = 64; st > 0; st >>= 1) {
        if (d < st) sm[d] += sm[d + st];
        __syncthreads();
    }
    float var = sm[0] / 128.f;
    h[idx] = c / sqrtf(var + 1e-5f) * gamma[d] + beta[d];
}

// ---------------- GEMM(128x128) + residual + LayerNorm fused (Wo, K=128) ----------------
__global__ void __launch_bounds__(256, 2)
gemm_ln128(const float* __restrict__ A, const float* __restrict__ W,
           const float* __restrict__ bias, float* __restrict__ hio,
           const float* __restrict__ gamma, const float* __restrict__ beta, int K) {
    __shared__ float As[2][8][128];
    __shared__ float Bs[2][8][128];
    const int tid = threadIdx.x;
    const int tx = tid & 15, ty = tid >> 4;
    const int m0 = blockIdx.y * 128;
    unsigned long long acc2[8][4];
#pragma unroll
    for (int i = 0; i < 8; i++)
#pragma unroll
        for (int j = 0; j < 4; j++) acc2[i][j] = 0ull;

    const int arow = tid >> 1, ahalf = tid & 1;
    const float* Aptr = A + (size_t)(m0 + arow) * K + ahalf * 4;
    const float* Wptr = W + (size_t)arow * K + ahalf * 4;

    const int KC = K >> 3;
    float4 ra = *(const float4*)(Aptr);
    float4 rb = *(const float4*)(Wptr);
    As[0][ahalf * 4 + 0][arow] = ra.x; As[0][ahalf * 4 + 1][arow] = ra.y;
    As[0][ahalf * 4 + 2][arow] = ra.z; As[0][ahalf * 4 + 3][arow] = ra.w;
    Bs[0][ahalf * 4 + 0][arow] = rb.x; Bs[0][ahalf * 4 + 1][arow] = rb.y;
    Bs[0][ahalf * 4 + 2][arow] = rb.z; Bs[0][ahalf * 4 + 3][arow] = rb.w;
    __syncthreads();

    int buf = 0;
    for (int kc = 0; kc < KC; kc++) {
        if (kc + 1 < KC) {
            ra = *(const float4*)(Aptr + (kc + 1) * 8);
            rb = *(const float4*)(Wptr + (kc + 1) * 8);
        }
#pragma unroll
        for (int k = 0; k < 8; k++) {
            ulonglong2 q0 = *(const ulonglong2*)&Bs[buf][k][tx * 4];
            ulonglong2 q1 = *(const ulonglong2*)&Bs[buf][k][64 + tx * 4];
            unsigned long long bp[4] = {q0.x, q0.y, q1.x, q1.y};
            float4 a0 = *(const float4*)&As[buf][k][ty * 4];
            float4 a1 = *(const float4*)&As[buf][k][64 + ty * 4];
            float aa[8] = {a0.x, a0.y, a0.z, a0.w, a1.x, a1.y, a1.z, a1.w};
#pragma unroll
            for (int i = 0; i < 8; i++) {
                unsigned long long ad = pack2(aa[i], aa[i]);
#pragma unroll
                for (int j = 0; j < 4; j++) ffma2(acc2[i][j], ad, bp[j]);
            }
        }
        if (kc + 1 < KC) {
            int nb = buf ^ 1;
            As[nb][ahalf * 4 + 0][arow] = ra.x; As[nb][ahalf * 4 + 1][arow] = ra.y;
            As[nb][ahalf * 4 + 2][arow] = ra.z; As[nb][ahalf * 4 + 3][arow] = ra.w;
            Bs[nb][ahalf * 4 + 0][arow] = rb.x; Bs[nb][ahalf * 4 + 1][arow] = rb.y;
            Bs[nb][ahalf * 4 + 2][arow] = rb.z; Bs[nb][ahalf * 4 + 3][arow] = rb.w;
            __syncthreads();
            buf = nb;
        }
    }

#pragma unroll
    for (int i = 0; i < 8; i++) {
        int m = m0 + ((i < 4) ? (ty * 4 + i) : (64 + ty * 4 + (i - 4)));
        float2 p0 = unpack2(acc2[i][0]), p1 = unpack2(acc2[i][1]);
        float2 p2 = unpack2(acc2[i][2]), p3 = unpack2(acc2[i][3]);
        float4 h0 = *(const float4*)&hio[(size_t)m * 128 + tx * 4];
        float4 h1 = *(const float4*)&hio[(size_t)m * 128 + 64 + tx * 4];
        float x[8];
        x[0] = p0.x + bias[tx * 4 + 0] + h0.x;
        x[1] = p0.y + bias[tx * 4 + 1] + h0.y;
        x[2] = p1.x + bias[tx * 4 + 2] + h0.z;
        x[3] = p1.y + bias[tx * 4 + 3] + h0.w;
        x[4] = p2.x + bias[64 + tx * 4 + 0] + h1.x;
        x[5] = p2.y + bias[64 + tx * 4 + 1] + h1.y;
        x[6] = p3.x + bias[64 + tx * 4 + 2] + h1.z;
        x[7] = p3.y + bias[64 + tx * 4 + 3] + h1.w;
        float s = 0.f;
#pragma unroll
        for (int j = 0; j < 8; j++) s += x[j];
#pragma unroll
        for (int off = 1; off < 16; off <<= 1)
            s += __shfl_xor_sync(0xffffffffu, s, off);
        float mean = s * 0.0078125f;
        float c[8], v = 0.f;
#pragma unroll
        for (int j = 0; j < 8; j++) { c[j] = x[j] - mean; v += c[j] * c[j]; }
#pragma unroll
        for (int off = 1; off < 16; off <<= 1)
            v += __shfl_xor_sync(0xffffffffu, v, off);
        float den = sqrtf(v * 0.0078125f + 1e-5f);
        float4 o0, o1;
        o0.x = c[0] / den * gamma[tx * 4 + 0] + beta[tx * 4 + 0];
        o0.y = c[1] / den * gamma[tx * 4 + 1] + beta[tx * 4 + 1];
        o0.z = c[2] / den * gamma[tx * 4 + 2] + beta[tx * 4 + 2];
        o0.w = c[3] / den * gamma[tx * 4 + 3] + beta[tx * 4 + 3];
        o1.x = c[4] / den * gamma[64 + tx * 4 + 0] + beta[64 + tx * 4 + 0];
        o1.y = c[5] / den * gamma[64 + tx * 4 + 1] + beta[64 + tx * 4 + 1];
        o1.z = c[6] / den * gamma[64 + tx * 4 + 2] + beta[64 + tx * 4 + 2];
        o1.w = c[7] / den * gamma[64 + tx * 4 + 3] + beta[64 + tx * 4 + 3];
        *(float4*)&hio[(size_t)m * 128 + tx * 4] = o0;
        *(float4*)&hio[(size_t)m * 128 + 64 + tx * 4] = o1;
    }
}

// ---------------- SGEMM 64x128, occ-3 (small GEMMs) ----------------
__global__ void __launch_bounds__(256, 3)
gemm64(const float* __restrict__ A, const float* __restrict__ W,
       const float* __restrict__ bias, float* __restrict__ C,
       int Nout, int K, int ldw, int relu) {
    __shared__ float As[2][8][64];
    __shared__ float Bs[2][8][128];
    const int tid = threadIdx.x;
    const int tx = tid & 15, ty = tid >> 4;
    const int m0 = blockIdx.y * 64, n0 = blockIdx.x * 128;
    unsigned long long acc2[4][4];
#pragma unroll
    for (int i = 0; i < 4; i++)
#pragma unroll
        for (int j = 0; j < 4; j++) acc2[i][j] = 0ull;

    const int arow = tid >> 1, ahalf = tid & 1;
    const bool aload = tid < 128;
    const float* Aptr = A + (size_t)(m0 + (aload ? arow : 0)) * K + ahalf * 4;
    const float* Wptr = W + (size_t)(n0 + arow) * ldw + ahalf * 4;

    const int KC = K >> 3;
    float4 ra = make_float4(0.f, 0.f, 0.f, 0.f), rb;
    if (aload) ra = *(const float4*)(Aptr);
    rb = *(const float4*)(Wptr);
    if (aload) {
        As[0][ahalf * 4 + 0][arow] = ra.x; As[0][ahalf * 4 + 1][arow] = ra.y;
        As[0][ahalf * 4 + 2][arow] = ra.z; As[0][ahalf * 4 + 3][arow] = ra.w;
    }
    Bs[0][ahalf * 4 + 0][arow] = rb.x; Bs[0][ahalf * 4 + 1][arow] = rb.y;
    Bs[0][ahalf * 4 + 2][arow] = rb.z; Bs[0][ahalf * 4 + 3][arow] = rb.w;
    __syncthreads();

    int buf = 0;
    for (int kc = 0; kc < KC; kc++) {
        if (kc + 1 < KC) {
            if (aload) ra = *(const float4*)(Aptr + (kc + 1) * 8);
            rb = *(const float4*)(Wptr + (kc + 1) * 8);
        }
#pragma unroll
        for (int k = 0; k < 8; k++) {
            ulonglong2 q0 = *(const ulonglong2*)&Bs[buf][k][tx * 4];
            ulonglong2 q1 = *(const ulonglong2*)&Bs[buf][k][64 + tx * 4];
            unsigned long long bp[4] = {q0.x, q0.y, q1.x, q1.y};
            float4 a0 = *(const float4*)&As[buf][k][ty * 4];
            float aa[4] = {a0.x, a0.y, a0.z, a0.w};
#pragma unroll
            for (int i = 0; i < 4; i++) {
                unsigned long long ad = pack2(aa[i], aa[i]);
#pragma unroll
                for (int j = 0; j < 4; j++) ffma2(acc2[i][j], ad, bp[j]);
            }
        }
        if (kc + 1 < KC) {
            int nb = buf ^ 1;
            if (aload) {
                As[nb][ahalf * 4 + 0][arow] = ra.x; As[nb][ahalf * 4 + 1][arow] = ra.y;
                As[nb][ahalf * 4 + 2][arow] = ra.z; As[nb][ahalf * 4 + 3][arow] = ra.w;
            }
            Bs[nb][ahalf * 4 + 0][arow] = rb.x; Bs[nb][ahalf * 4 + 1][arow] = rb.y;
            Bs[nb][ahalf * 4 + 2][arow] = rb.z; Bs[nb][ahalf * 4 + 3][arow] = rb.w;
            __syncthreads();
            buf = nb;
        }
    }

    float bv[8];
#pragma unroll
    for (int j = 0; j < 4; j++) {
        bv[j]     = bias ? bias[n0 + tx * 4 + j]      : 0.f;
        bv[4 + j] = bias ? bias[n0 + 64 + tx * 4 + j] : 0.f;
    }
#pragma unroll
    for (int i = 0; i < 4; i++) {
        int m = m0 + ty * 4 + i;
        float2 p0 = unpack2(acc2[i][0]), p1 = unpack2(acc2[i][1]);
        float2 p2 = unpack2(acc2[i][2]), p3 = unpack2(acc2[i][3]);
        float4 o0, o1;
        o0.x = p0.x + bv[0]; o0.y = p0.y + bv[1]; o0.z = p1.x + bv[2]; o0.w = p1.y + bv[3];
        o1.x = p2.x + bv[4]; o1.y = p2.y + bv[5]; o1.z = p3.x + bv[6]; o1.w = p3.y + bv[7];
        if (relu) {
            o0.x = fmaxf(o0.x, 0.f); o0.y = fmaxf(o0.y, 0.f);
            o0.z = fmaxf(o0.z, 0.f); o0.w = fmaxf(o0.w, 0.f);
            o1.x = fmaxf(o1.x, 0.f); o1.y = fmaxf(o1.y, 0.f);
            o1.z = fmaxf(o1.z, 0.f); o1.w = fmaxf(o1.w, 0.f);
        }
        *(float4*)&C[(size_t)m * Nout + n0 + tx * 4] = o0;
        *(float4*)&C[(size_t)m * Nout + n0 + 64 + tx * 4] = o1;
    }
}

// ---------------- batched bounded GEMM (S1) ----------------
__global__ void __launch_bounds__(256, 3)
gemm_batched(const float* __restrict__ A0, const float* __restrict__ W0,
             float* __restrict__ C0, int M, int Nout, int K,
             long long sA, long long sW, long long sC) {
    __shared__ float As[2][8][64];
    __shared__ float Bs[2][8][128];
    const float* A = A0 + (long long)blockIdx.z * sA;
    const float* W = W0 + (long long)blockIdx.z * sW;
    float* C = C0 + (long long)blockIdx.z * sC;
    const int tid = threadIdx.x;
    const int tx = tid & 15, ty = tid >> 4;
    const int m0 = blockIdx.y * 64, n0 = blockIdx.x * 128;
    unsigned long long acc2[4][4];
#pragma unroll
    for (int i = 0; i < 4; i++)
#pragma unroll
        for (int j = 0; j < 4; j++) acc2[i][j] = 0ull;

    const int arow = tid >> 1, ahalf = tid & 1;
    const bool aload = tid < 128;
    const bool aok = aload && (m0 + arow < M);
    const bool wok = (n0 + arow < Nout);
    const float* Aptr = A + (size_t)(aok ? (m0 + arow) : 0) * K + ahalf * 4;
    const float* Wptr = W + (size_t)(wok ? (n0 + arow) : 0) * K + ahalf * 4;

    const int KC = K >> 3;
    float4 ra = make_float4(0.f, 0.f, 0.f, 0.f), rb;
    if (aload) ra = *(const float4*)(Aptr);
    rb = *(const float4*)(Wptr);
    if (aload) {
        As[0][ahalf * 4 + 0][arow] = ra.x; As[0][ahalf * 4 + 1][arow] = ra.y;
        As[0][ahalf * 4 + 2][arow] = ra.z; As[0][ahalf * 4 + 3][arow] = ra.w;
    }
    Bs[0][ahalf * 4 + 0][arow] = rb.x; Bs[0][ahalf * 4 + 1][arow] = rb.y;
    Bs[0][ahalf * 4 + 2][arow] = rb.z; Bs[0][ahalf * 4 + 3][arow] = rb.w;
    __syncthreads();

    int buf = 0;
    for (int kc = 0; kc < KC; kc++) {
        if (kc + 1 < KC) {
            if (aload) ra = *(const float4*)(Aptr + (kc + 1) * 8);
            rb = *(const float4*)(Wptr + (kc + 1) * 8);
        }
#pragma unroll
        for (int k = 0; k < 8; k++) {
            ulonglong2 q0 = *(const ulonglong2*)&Bs[buf][k][tx * 4];
            ulonglong2 q1 = *(const ulonglong2*)&Bs[buf][k][64 + tx * 4];
            unsigned long long bp[4] = {q0.x, q0.y, q1.x, q1.y};
            float4 a0 = *(const float4*)&As[buf][k][ty * 4];
            float aa[4] = {a0.x, a0.y, a0.z, a0.w};
#pragma unroll
            for (int i = 0; i < 4; i++) {
                unsigned long long ad = pack2(aa[i], aa[i]);
#pragma unroll
                for (int j = 0; j < 4; j++) ffma2(acc2[i][j], ad, bp[j]);
            }
        }
        if (kc + 1 < KC) {
            int nb = buf ^ 1;
            if (aload) {
                As[nb][ahalf * 4 + 0][arow] = ra.x; As[nb][ahalf * 4 + 1][arow] = ra.y;
                As[nb][ahalf * 4 + 2][arow] = ra.z; As[nb][ahalf * 4 + 3][arow] = ra.w;
            }
            Bs[nb][ahalf * 4 + 0][arow] = rb.x; Bs[nb][ahalf * 4 + 1][arow] = rb.y;
            Bs[nb][ahalf * 4 + 2][arow] = rb.z; Bs[nb][ahalf * 4 + 3][arow] = rb.w;
            __syncthreads();
            buf = nb;
        }
    }

#pragma unroll
    for (int i = 0; i < 4; i++) {
        int m = m0 + ty * 4 + i;
        if (m >= M) continue;
        float2 p0 = unpack2(acc2[i][0]), p1 = unpack2(acc2[i][1]);
        float2 p2 = unpack2(acc2[i][2]), p3 = unpack2(acc2[i][3]);
        int c0 = n0 + tx * 4, c1 = n0 + 64 + tx * 4;
        if (c0 + 3 < Nout) {
            float4 o; o.x = p0.x; o.y = p0.y; o.z = p1.x; o.w = p1.y;
            *(float4*)&C[(size_t)m * Nout + c0] = o;
        }
        if (c1 + 3 < Nout) {
            float4 o; o.x = p2.x; o.y = p2.y; o.z = p3.x; o.w = p3.y;
            *(float4*)&C[(size_t)m * Nout + c1] = o;
        }
    }
}

// ---------------- attention ----------------
__global__ void __launch_bounds__(256)
attention_smem(const float* __restrict__ qkv, float* __restrict__ out) {
    int bh = blockIdx.x;
    int b = bh >> 3, h = bh & 7;
    __shared__ float QsT[DH_][208], KsT[DH_][208], VsT[DH_][208];
    const float* base = qkv + (size_t)b * N_ * 384 + h * DH_;
    int tid = threadIdx.x;
    for (int i = tid; i < N_ * DH_; i += 256) {
        int n = i >> 4, d = i & 15;
        const float* rp = base + (size_t)n * 384 + d;
        QsT[d][n] = rp[0];
        KsT[d][n] = rp[128];
        VsT[d][n] = rp[256];
    }
    __syncthreads();
    int warp = tid >> 5, lane = tid & 31;
    for (int q = warp; q < N_; q += 8) {
        float qv[DH_];
#pragma unroll
        for (int d = 0; d < DH_; d++) qv[d] = QsT[d][q];
        float s[7];
        float mx = -INFINITY;
#pragma unroll
        for (int j = 0; j < 7; j++) {
            int k = lane + 32 * j;
            float a = 0.f;
            if (k < N_) {
#pragma unroll
                for (int d = 0; d < DH_; d++) a += qv[d] * KsT[d][k];
                a *= 0.25f;
            } else a = -INFINITY;
            s[j] = a;
            mx = fmaxf(mx, a);
        }
#pragma unroll
        for (int off = 16; off; off >>= 1)
            mx = fmaxf(mx, __shfl_xor_sync(0xffffffffu, mx, off));
        float p[7];
        float sum = 0.f;
#pragma unroll
        for (int j = 0; j < 7; j++) {
            int k = lane + 32 * j;
            p[j] = (k < N_) ? expf(s[j] - mx) : 0.f;
            sum += p[j];
        }
#pragma unroll
        for (int off = 16; off; off >>= 1)
            sum += __shfl_xor_sync(0xffffffffu, sum, off);
        float inv = 1.f / sum;
        float o[DH_];
#pragma unroll
        for (int d = 0; d < DH_; d++) o[d] = 0.f;
#pragma unroll
        for (int j = 0; j < 7; j++) {
            int k = lane + 32 * j;
            if (k < N_) {
                float wgt = p[j] * inv;
#pragma unroll
                for (int d = 0; d < DH_; d++) o[d] += wgt * VsT[d][k];
            }
        }
#pragma unroll
        for (int d = 0; d < DH_; d++) {
            float v = o[d];
#pragma unroll
            for (int off = 16; off; off >>= 1)
                v += __shfl_xor_sync(0xffffffffu, v, off);
            if (lane == d)
                out[((size_t)b * N_ + q) * D_ + h * DH_ + d] = v;
        }
    }
}

// ---------------- small precompute kernels ----------------
__global__ void compute_M_kernel(const float* __restrict__ Wq, const float* __restrict__ Wctx) {
    int d = blockIdx.y;
    int c = blockIdx.x * blockDim.x + threadIdx.x;
    if (c >= 3 * D_) return;
    float acc = 0.f;
    for (int k = 0; k < D_; k++) acc += Wq[d * D_ + k] * Wctx[k * (3 * D_) + c];
    g_M[d * (3 * D_) + c] = acc;
}

__global__ void compute_vecs_kernel(const float* __restrict__ Wq, const float* __restrict__ bctx,
                                    const float* __restrict__ Wcap, const float* __restrict__ bcap) {
    int d = threadIdx.x;
    float a = 0.f, u = 0.f, bq = 0.f;
    for (int k = 0; k < D_; k++) {
        float m = g_M[d * (3 * D_) + 2 * D_ + k];
        a += m * bcap[k];
        u += m * Wcap[k];
        bq += Wq[d * D_ + k] * bctx[k];
    }
    g_vconst[d] = a + bq;
    g_vu[d] = u;
}

__global__ void compute_gctx_kernel() {
    int b = blockIdx.x, d = threadIdx.x;
    float s = 0.f;
    for (int n = 0; n < N_; n++) s += g_h[((size_t)b * N_ + n) * D_ + d];
    g_gctx[b * D_ + d] = s / (float)N_;
}

__global__ void compute_qctx_kernel() {
    int b = blockIdx.x, d = threadIdx.x;
    float a = g_vconst[d];
    for (int k = 0; k < D_; k++) a += g_M[d * (3 * D_) + D_ + k] * g_gctx[b * D_ + k];
    g_qctx[b * D_ + d] = a;
}

__global__ void compute_CU_kernel() {
    int i = blockIdx.x * blockDim.x + threadIdx.x;
    if (i >= ROWS) return;
    int b = i / N_;
    const float* kr = g_kmat + (size_t)i * D_;
    float c = 0.f, u = 0.f;
    for (int d = 0; d < D_; d++) {
        c += kr[d] * g_qctx[b * D_ + d];
        u += kr[d] * g_vu[d];
    }
    g_C[i] = c;
    g_U[i] = u;
}

// ---------------- decode: 256-thread block, inline gumbel on feasible only ----------------
__global__ void __launch_bounds__(256)
decode_kernel(float* __restrict__ path_out, float* __restrict__ lp_out) {
    int b = blockIdx.x;
    int t = threadIdx.x;
    int w = t >> 5, lane = t & 31;
    __shared__ unsigned char s_vis[256];
    __shared__ float s_masked[256];
    __shared__ unsigned s_bf[8], s_bu[8];
    __shared__ float s_wmax[8], s_wkey[8], s_wsum[8];
    __shared__ int s_widx[8];
    __shared__ float s_rem, s_acc;
    __shared__ int s_cur, s_done, s_cnt;

    s_vis[t] = 0;
    if (t == 0) {
        s_rem = 1.0f; s_cur = 0; s_done = 0; s_cnt = N_ - 1; s_acc = 0.f;
        path_out[(size_t)b * (STEPS + 1)] = 0.0f;
    }
    float drv = 0.f, Cv = 0.f, Uv = 0.f, s1v = 0.f;
    if (t < N_) {
        drv = g_dr[b * N_ + t];
        Cv = g_C[b * N_ + t];
        Uv = g_U[b * N_ + t];
        s1v = g_S1[(size_t)(b * N_ + 0) * N_ + t];
    }
    __syncthreads();

    for (int step = 0; step < STEPS; step++) {
        float rem = s_rem;
        int cur = s_cur;
        int done = s_done;
        bool vis = s_vis[t] != 0;

        bool feas = (t >= 1 && t < N_) && !vis && (drv <= rem);
        bool unv = (t >= 1 && t < N_) && !vis;
        unsigned bfm = __ballot_sync(0xffffffffu, feas);
        unsigned bum = __ballot_sync(0xffffffffu, unv);
        if (lane == 0) { s_bf[w] = bfm; s_bu[w] = bum; }
        __syncthreads();
        unsigned fb = 0, ub = 0;
#pragma unroll
        for (int i = 0; i < 8; i++) { fb |= s_bf[i]; ub |= s_bu[i]; }
        bool has_feas = fb != 0, all_served = (ub == 0);

        bool at_depot = (cur == 0) && !done;
        bool not_depot = (cur != 0) && !done;
        bool depot_mask = (at_depot && has_feas) ||
                          (not_depot && has_feas && !all_served);
        bool force_depot = (all_served && (cur != 0) && !done) ||
                           (not_depot && !has_feas) || done;

        float m = -INFINITY, keyv = -INFINITY;
        if (t < N_) {
            bool infeas = vis || (drv > rem);
            if (t == 0) infeas = infeas || depot_mask;
            float logit = (s1v + Cv + rem * Uv) / SQRTD;
            m = infeas ? -1e9f : logit;
            s_masked[t] = m;
            keyv = m;
            if (!infeas) {
                uint2 y = threefry2x32(c_keys.x[step], c_keys.y[step],
                                       0u, (uint32_t)(b * N_ + t));
                uint32_t bits = y.x ^ y.y;
                float f = __uint_as_float((bits >> 9) | 0x3f800000u) - 1.0f;
                float u = (f == 0.f) ? 1.17549435e-38f : f;
                keyv = m - logf(-logf(u));
            }
        }
        float mxm = m, kv = keyv;
        int ki = t;
#pragma unroll
        for (int off = 16; off; off >>= 1) {
            mxm = fmaxf(mxm, __shfl_xor_sync(0xffffffffu, mxm, off));
            float kv2 = __shfl_xor_sync(0xffffffffu, kv, off);
            int ki2 = __shfl_xor_sync(0xffffffffu, ki, off);
            if (kv2 > kv || (kv2 == kv && ki2 < ki)) { kv = kv2; ki = ki2; }
        }
        float e = (t < N_) ? expf(m - mxm) : 0.f;
#pragma unroll
        for (int off = 16; off; off >>= 1)
            e += __shfl_xor_sync(0xffffffffu, e, off);
        if (lane == 0) { s_wmax[w] = mxm; s_wkey[w] = kv; s_widx[w] = ki; s_wsum[w] = e; }
        __syncthreads();
        float mx = s_wmax[0], bk = s_wkey[0];
        int bi = s_widx[0];
#pragma unroll
        for (int i = 1; i < 8; i++) {
            mx = fmaxf(mx, s_wmax[i]);
            float k2 = s_wkey[i];
            if (k2 > bk) { bk = k2; bi = s_widx[i]; }
        }
        int ncur = force_depot ? 0 : bi;
        float s1n = 0.f;
        if (step + 1 < STEPS && t < N_)
            s1n = g_S1[(size_t)(b * N_ + ncur) * N_ + t];
        if (t == 0) {
            float sum = 0.f;
#pragma unroll
            for (int i = 0; i < 8; i++) sum += s_wsum[i] * expf(s_wmax[i] - mx);
            int sel = bi;
            float slp = s_masked[sel] - mx - logf(sum);
            if (force_depot) { sel = 0; slp = 0.f; }
            bool isd = (sel == 0);
            float take = g_dr[b * N_ + sel];
            float nr = isd ? 1.0f : (rem - take);
            nr = fminf(fmaxf(nr, 0.f), 1.f);
            s_rem = nr;
            if (!isd && !s_vis[sel]) { s_vis[sel] = 1; s_cnt--; }
            s_cur = sel;
            s_done = done || (s_cnt == 0 && isd);
            s_acc += slp;
            path_out[(size_t)b * (STEPS + 1) + 1 + step] = (float)sel;
        }
        __syncthreads();
        s1v = s1n;
    }
    if (t == 0 && lp_out) lp_out[b] = s_acc;
}

// ---------------- launch ----------------
extern "C" void kernel_launch(void* const* d_in, const int* in_sizes, int n_in,
                              void* d_out, int out_size) {
    int perm[23];
    for (int i = 0; i < 23; i++) perm[i] = i;
    if (n_in >= 23 && in_sizes[0] == 786432) {
        const int m[23] = {15,16,14,17,18,7,13,5,12,0,8,1,9,20,19,22,21,6,4,2,10,3,11};
        for (int i = 0; i < 23; i++) perm[i] = m[i];
    }
    const float* coords   = (const float*)d_in[perm[0]];
    const float* demands  = (const float*)d_in[perm[1]];
    const float* capacity = (const float*)d_in[perm[2]];
    const float* embed_W  = (const float*)d_in[perm[3]];
    const float* embed_b  = (const float*)d_in[perm[4]];
    const float* Wqkv     = (const float*)d_in[perm[5]];
    const float* bqkv     = (const float*)d_in[perm[6]];
    const float* Wo       = (const float*)d_in[perm[7]];
    const float* bo       = (const float*)d_in[perm[8]];
    const float* W1       = (const float*)d_in[perm[9]];
    const float* b1       = (const float*)d_in[perm[10]];
    const float* W2       = (const float*)d_in[perm[11]];
    const float* b2       = (const float*)d_in[perm[12]];
    const float* ln1_g    = (const float*)d_in[perm[13]];
    const float* ln1_b    = (const float*)d_in[perm[14]];
    const float* ln2_g    = (const float*)d_in[perm[15]];
    const float* ln2_b    = (const float*)d_in[perm[16]];
    const float* Wq       = (const float*)d_in[perm[17]];
    const float* Wk       = (const float*)d_in[perm[18]];
    const float* Wcap     = (const float*)d_in[perm[19]];
    const float* bcap     = (const float*)d_in[perm[20]];
    const float* Wctx     = (const float*)d_in[perm[21]];
    const float* bctx     = (const float*)d_in[perm[22]];

    float *g_h_p, *g_qkv_p, *g_att_p, *g_ffn_p, *g_part_p, *g_kmat_p, *g_hM_p, *g_S1_p, *g_M_p;
    cudaGetSymbolAddress((void**)&g_h_p, g_h);
    cudaGetSymbolAddress((void**)&g_qkv_p, g_qkv);
    cudaGetSymbolAddress((void**)&g_att_p, g_att);
    cudaGetSymbolAddress((void**)&g_ffn_p, g_ffn);
    cudaGetSymbolAddress((void**)&g_part_p, g_part);
    cudaGetSymbolAddress((void**)&g_kmat_p, g_kmat);
    cudaGetSymbolAddress((void**)&g_hM_p, g_hM);
    cudaGetSymbolAddress((void**)&g_S1_p, g_S1);
    cudaGetSymbolAddress((void**)&g_M_p, g_M);

    embed_kernel<<<ROWS, 128>>>(coords, demands, capacity, embed_W, embed_b);

    for (int i = 0; i < L_; i++) {
        gemm128<<<dim3(3, 200), 256>>>(
            g_h_p, Wqkv + (size_t)i * 384 * 128, bqkv + i * 384, g_qkv_p,
            384, 128, 128, 0);
        attention_smem<<<B_ * H_, 256>>>(g_qkv_p, g_att_p);
        gemm_ln128<<<dim3(1, 200), 256>>>(
            g_att_p, Wo + (size_t)i * 128 * 128, bo + i * 128, g_h_p,
            ln1_g + i * 128, ln1_b + i * 128, 128);
        gemm128<<<dim3(16, 200), 256>>>(
            g_h_p, W1 + (size_t)i * F_ * 128, b1 + i * F_, g_ffn_p,
            F_, 128, 128, 1);
        // FFN2 split-K=4: 800 blocks instead of 200
        gemm_sk128<<<dim3(1, 200, 4), 256>>>(
            g_ffn_p, W2 + (size_t)i * 128 * F_, g_part_p, 512, F_, F_);
        ln_join4<<<ROWS, 128>>>(g_h_p, b2 + i * 128, ln2_g + i * 128, ln2_b + i * 128);
    }

    compute_gctx_kernel<<<B_, 128>>>();
    compute_M_kernel<<<dim3(3, 128), 128>>>(Wq, Wctx);
    compute_vecs_kernel<<<1, 128>>>(Wq, bctx, Wcap, bcap);
    compute_qctx_kernel<<<B_, 128>>>();
    gemm64<<<dim3(1, 400), 256>>>(g_h_p, Wk, nullptr, g_kmat_p, 128, 128, 128, 0);
    gemm64<<<dim3(1, 400), 256>>>(g_h_p, g_M_p, nullptr, g_hM_p, 128, 128, 384, 0);
    gemm_batched<<<dim3(2, 4, B_), 256>>>(
        g_hM_p, g_kmat_p, g_S1_p, N_, N_, 128,
        (long long)N_ * 128, (long long)N_ * 128, (long long)N_ * N_);
    compute_CU_kernel<<<(ROWS + 255) / 256, 256>>>();

    float* out_f = (float*)d_out;
    float* lp_out = (out_size >= B_ * (STEPS + 1) + B_) ? (out_f + B_ * (STEPS + 1)) : nullptr;
    decode_kernel<<<B_, 256>>>(out_f, lp_out);
}